// round 2
// baseline (speedup 1.0000x reference)
#include <cuda_runtime.h>

#define NN 10000
#define EE 320000
#define NG_ 16

// ---------------- scratch (static device memory; no allocations) ----------------
__device__ float  g_s[NN*64];      // s after lp
__device__ float4 g_v4[NN*32];     // v after lp, (x,y,z,0)
__device__ float  g_scs[NN*64];    // self-connection scalar
__device__ float  g_scv[NN*96];    // self-connection vector [n][w*3+i]
__device__ float  g_accs[NN*64];   // edge-aggregated scalar
__device__ float  g_accv[NN*96];   // edge-aggregated vector
__device__ float  g_ns[NN*64];
__device__ float  g_nv[NN*96];
__device__ float  g_wmlp[(long long)EE*96];   // per-edge MLP output
__device__ float  g_gstat[4*NG_];  // m, q, p, count
__device__ float  g_gout[3*NG_];   // mu, inv_std_s, inv_std_v

__device__ __forceinline__ float sig_(float x){ return 1.f/(1.f+__expf(-x)); }

// ---------------- zero accumulators ----------------
__global__ void k_zero(){
  int i = blockIdx.x*blockDim.x + threadIdx.x;
  if (i < NN*64) g_accs[i] = 0.f;
  int j = i - NN*64;
  if (j >= 0 && j < NN*96) g_accv[j] = 0.f;
  int k = i - NN*160;
  if (k >= 0 && k < 4*NG_) g_gstat[k] = 0.f;
}

// ---------------- node pre: lp projections + self connection ----------------
__global__ void __launch_bounds__(512) k_node_pre(const float* __restrict__ nf,
                           const float* __restrict__ oh,
                           const float* __restrict__ lpWs, const float* __restrict__ lpbs,
                           const float* __restrict__ lpWv,
                           const float* __restrict__ scWs, const float* __restrict__ scWv){
  extern __shared__ float sm[];
  float2* WsS  = (float2*)sm;                 // lp_Ws 4096 f
  float*  WvS  = sm + 4096;                   // lp_Wv 1024 f
  float2* sWsS = (float2*)(sm + 5120);        // sc_Ws 16384 f
  float*  sWvS = sm + 21504;                  // sc_Wv 4096 f
  float*  bsS  = sm + 25600;                  // lp_bs 64
  float*  stage= sm + 25664;                  // per-warp 192 f

  for (int i=threadIdx.x;i<4096;i+=blockDim.x) sm[i]=lpWs[i];
  for (int i=threadIdx.x;i<1024;i+=blockDim.x) WvS[i]=lpWv[i];
  for (int i=threadIdx.x;i<16384;i+=blockDim.x) sm[5120+i]=scWs[i];
  for (int i=threadIdx.x;i<4096;i+=blockDim.x) sWvS[i]=scWv[i];
  for (int i=threadIdx.x;i<64;i+=blockDim.x) bsS[i]=lpbs[i];
  __syncthreads();

  int warp = threadIdx.x>>5, lane = threadIdx.x&31, wpb = blockDim.x>>5;
  float*  sS  = stage + warp*192;
  float4* vS  = (float4*)(sS + 64);

  for (int n = blockIdx.x*wpb + warp; n < NN; n += gridDim.x*wpb){
    const float* row = nf + n*160;
    sS[lane] = row[lane]; sS[32+lane] = row[32+lane];
    vS[lane] = make_float4(row[64+3*lane], row[65+3*lane], row[66+3*lane], 0.f);
    const float* o4 = oh + n*4;
    int sp = (o4[1]>0.5f)?1:((o4[2]>0.5f)?2:((o4[3]>0.5f)?3:0));
    __syncwarp();

    float a0=0.f,a1=0.f,c0=0.f,c1=0.f;
    #pragma unroll 4
    for (int u=0;u<64;u++){
      float x = sS[u];
      float2 w  = WsS[u*32+lane];
      float2 w2 = sWsS[(u*4+sp)*32+lane];
      a0+=x*w.x; a1+=x*w.y; c0+=x*w2.x; c1+=x*w2.y;
    }
    g_s[n*64+2*lane]   = a0*0.125f + bsS[2*lane];
    g_s[n*64+2*lane+1] = a1*0.125f + bsS[2*lane+1];
    g_scs[n*64+2*lane]   = c0*0.0625f;
    g_scs[n*64+2*lane+1] = c1*0.0625f;

    float vx=0.f,vy=0.f,vz=0.f,cx=0.f,cy=0.f,cz=0.f;
    #pragma unroll 4
    for (int u=0;u<32;u++){
      float4 x = vS[u];
      float w  = WvS[u*32+lane];
      float w2 = sWvS[(u*4+sp)*32+lane];
      vx+=x.x*w;  vy+=x.y*w;  vz+=x.z*w;
      cx+=x.x*w2; cy+=x.y*w2; cz+=x.z*w2;
    }
    g_v4[n*32+lane] = make_float4(vx*0.17677670f, vy*0.17677670f, vz*0.17677670f, 0.f);
    g_scv[n*96+3*lane]   = cx*0.08838835f;
    g_scv[n*96+3*lane+1] = cy*0.08838835f;
    g_scv[n*96+3*lane+2] = cz*0.08838835f;
    __syncwarp();
  }
}

// ---------------- per-edge MLP (128->64->64->96), 2 edges/warp ----------------
__global__ void __launch_bounds__(512) k_mlp(const float* __restrict__ ele,
   const float* __restrict__ W1, const float* __restrict__ b1,
   const float* __restrict__ W2, const float* __restrict__ b2,
   const float* __restrict__ W3, const float* __restrict__ b3){
  extern __shared__ float sm[];
  float2* W1S = (float2*)sm;              // 8192 f
  float2* W2S = (float2*)(sm+8192);       // 4096 f
  float4* W3S = (float4*)(sm+12288);      // 8192 f
  float* b1S = sm+20480; float* b2S = sm+20544; float* b3S = sm+20608;
  float* stage = sm+20704;                // per-warp 512 f

  for (int i=threadIdx.x;i<8192;i+=blockDim.x) sm[i]=W1[i];
  for (int i=threadIdx.x;i<4096;i+=blockDim.x) sm[8192+i]=W2[i];
  for (int i=threadIdx.x;i<2048;i+=blockDim.x){
    int j=i>>5, l=i&31;
    W3S[i]=make_float4(W3[j*96+l], W3[j*96+32+l], W3[j*96+64+l], 0.f);
  }
  for (int i=threadIdx.x;i<64;i+=blockDim.x){ b1S[i]=b1[i]; b2S[i]=b2[i]; }
  for (int i=threadIdx.x;i<96;i+=blockDim.x) b3S[i]=b3[i];
  __syncthreads();

  int warp=threadIdx.x>>5, lane=threadIdx.x&31, wpb=blockDim.x>>5;
  float* eA = stage + warp*512;  // 128
  float* hA = eA+128;            // 64
  float* gA = hA+64;             // 64
  float* eB = eA+256; float* hB = hA+256; float* gB = gA+256;

  const int pairs = EE/2;
  for (int p = blockIdx.x*wpb+warp; p<pairs; p+=gridDim.x*wpb){
    long long e0 = 2LL*p, e1 = e0+1;
    const float* ra = ele + e0*128;
    const float* rb = ele + e1*128;
    #pragma unroll
    for (int c=0;c<4;c++){ eA[c*32+lane]=ra[c*32+lane]; eB[c*32+lane]=rb[c*32+lane]; }
    __syncwarp();
    float a0=0.f,a1=0.f,d0=0.f,d1=0.f;
    #pragma unroll 4
    for (int j=0;j<128;j+=4){
      float4 x=*(float4*)(eA+j);
      float4 y=*(float4*)(eB+j);
      float2 w;
      w=W1S[(j  )*32+lane]; a0+=x.x*w.x; a1+=x.x*w.y; d0+=y.x*w.x; d1+=y.x*w.y;
      w=W1S[(j+1)*32+lane]; a0+=x.y*w.x; a1+=x.y*w.y; d0+=y.y*w.x; d1+=y.y*w.y;
      w=W1S[(j+2)*32+lane]; a0+=x.z*w.x; a1+=x.z*w.y; d0+=y.z*w.x; d1+=y.z*w.y;
      w=W1S[(j+3)*32+lane]; a0+=x.w*w.x; a1+=x.w*w.y; d0+=y.w*w.x; d1+=y.w*w.y;
    }
    a0+=b1S[2*lane]; a1+=b1S[2*lane+1]; d0+=b1S[2*lane]; d1+=b1S[2*lane+1];
    hA[2*lane]=a0*sig_(a0); hA[2*lane+1]=a1*sig_(a1);
    hB[2*lane]=d0*sig_(d0); hB[2*lane+1]=d1*sig_(d1);
    __syncwarp();
    a0=0.f;a1=0.f;d0=0.f;d1=0.f;
    #pragma unroll 4
    for (int j=0;j<64;j+=4){
      float4 x=*(float4*)(hA+j);
      float4 y=*(float4*)(hB+j);
      float2 w;
      w=W2S[(j  )*32+lane]; a0+=x.x*w.x; a1+=x.x*w.y; d0+=y.x*w.x; d1+=y.x*w.y;
      w=W2S[(j+1)*32+lane]; a0+=x.y*w.x; a1+=x.y*w.y; d0+=y.y*w.x; d1+=y.y*w.y;
      w=W2S[(j+2)*32+lane]; a0+=x.z*w.x; a1+=x.z*w.y; d0+=y.z*w.x; d1+=y.z*w.y;
      w=W2S[(j+3)*32+lane]; a0+=x.w*w.x; a1+=x.w*w.y; d0+=y.w*w.x; d1+=y.w*w.y;
    }
    a0+=b2S[2*lane]; a1+=b2S[2*lane+1]; d0+=b2S[2*lane]; d1+=b2S[2*lane+1];
    gA[2*lane]=a0*sig_(a0); gA[2*lane+1]=a1*sig_(a1);
    gB[2*lane]=d0*sig_(d0); gB[2*lane+1]=d1*sig_(d1);
    __syncwarp();
    float c0=0.f,c1=0.f,c2=0.f,f0=0.f,f1=0.f,f2=0.f;
    #pragma unroll 4
    for (int j=0;j<64;j+=4){
      float4 x=*(float4*)(gA+j);
      float4 y=*(float4*)(gB+j);
      float4 w;
      w=W3S[(j  )*32+lane]; c0+=x.x*w.x; c1+=x.x*w.y; c2+=x.x*w.z; f0+=y.x*w.x; f1+=y.x*w.y; f2+=y.x*w.z;
      w=W3S[(j+1)*32+lane]; c0+=x.y*w.x; c1+=x.y*w.y; c2+=x.y*w.z; f0+=y.y*w.x; f1+=y.y*w.y; f2+=y.y*w.z;
      w=W3S[(j+2)*32+lane]; c0+=x.z*w.x; c1+=x.z*w.y; c2+=x.z*w.z; f0+=y.z*w.x; f1+=y.z*w.y; f2+=y.z*w.z;
      w=W3S[(j+3)*32+lane]; c0+=x.w*w.x; c1+=x.w*w.y; c2+=x.w*w.z; f0+=y.w*w.x; f1+=y.w*w.y; f2+=y.w*w.z;
    }
    float* woA = g_wmlp + e0*96;
    float* woB = g_wmlp + e1*96;
    woA[lane]=c0+b3S[lane]; woA[32+lane]=c1+b3S[32+lane]; woA[64+lane]=c2+b3S[64+lane];
    woB[lane]=f0+b3S[lane]; woB[32+lane]=f1+b3S[32+lane]; woB[64+lane]=f2+b3S[64+lane];
    __syncwarp();
  }
}

// ---------------- edge interaction + scatter, 2 edges/warp ----------------
__global__ void __launch_bounds__(512) k_edge(const int* __restrict__ eidx,
   const float* __restrict__ esh, const float* __restrict__ efea,
   const float* __restrict__ Wss0, const float* __restrict__ Wvv0,
   const float* __restrict__ Wssg, const float* __restrict__ Wvvg,
   const float* __restrict__ Wsv1, const float* __restrict__ Wvs1){
  extern __shared__ float sm[];
  float4* F1 = (float4*)sm;            // 192x32 f4: (ss0[2l],ss0[2l+1],ssg[l],sv1[l])
  float4* F2 = (float4*)(sm+24576);    // 96x32  f4: (vv0[2l],vv0[2l+1],vvg[l],vs1[l])
  float* stage = sm + 36864;           // per-warp 1152 f

  for (int i=threadIdx.x;i<6144;i+=blockDim.x){
    int u=i>>5, l=i&31;
    F1[i]=make_float4(Wss0[u*64+2*l], Wss0[u*64+2*l+1], Wssg[u*32+l], Wsv1[u*32+l]);
  }
  for (int i=threadIdx.x;i<3072;i+=blockDim.x){
    int u=i>>5, l=i&31;
    F2[i]=make_float4(Wvv0[u*64+2*l], Wvv0[u*64+2*l+1], Wvvg[u*32+l], Wvs1[u*32+l]);
  }
  __syncthreads();

  int warp=threadIdx.x>>5, lane=threadIdx.x&31, wpb=blockDim.x>>5;
  float*  s1a = stage + warp*1152;      // 192
  float4* vda = (float4*)(s1a+192);     // 96 f4
  float*  s1b = s1a+576;
  float4* vdb = (float4*)(s1b+192);
  const float inv3 = 0.57735027f, invfan = 0.058925565f;
  const int pairs = EE/2;

  for (int p = blockIdx.x*wpb+warp; p<pairs; p+=gridDim.x*wpb){
    int e0 = 2*p, e1 = e0+1;
    int ni0=eidx[e0], nj0=eidx[EE+e0];
    int ni1=eidx[e1], nj1=eidx[EE+e1];
    float4 shA = *(const float4*)(esh + (long long)e0*4);
    float4 shB = *(const float4*)(esh + (long long)e1*4);
    const float* ra = efea + (long long)e0*160;
    const float* rb = efea + (long long)e1*160;
    s1a[lane]=g_s[ni0*64+lane];      s1a[32+lane]=g_s[ni0*64+32+lane];
    s1a[64+lane]=g_s[nj0*64+lane];   s1a[96+lane]=g_s[nj0*64+32+lane];
    s1a[128+lane]=ra[lane];          s1a[160+lane]=ra[32+lane];
    s1b[lane]=g_s[ni1*64+lane];      s1b[32+lane]=g_s[ni1*64+32+lane];
    s1b[64+lane]=g_s[nj1*64+lane];   s1b[96+lane]=g_s[nj1*64+32+lane];
    s1b[128+lane]=rb[lane];          s1b[160+lane]=rb[32+lane];
    {
      float4 v = g_v4[ni0*32+lane];
      v.w=(v.x*shA.y+v.y*shA.z+v.z*shA.w)*inv3; vda[lane]=v;
      v = g_v4[nj0*32+lane];
      v.w=(v.x*shA.y+v.y*shA.z+v.z*shA.w)*inv3; vda[32+lane]=v;
      float ex=ra[64+3*lane], ey=ra[65+3*lane], ez=ra[66+3*lane];
      vda[64+lane]=make_float4(ex,ey,ez,(ex*shA.y+ey*shA.z+ez*shA.w)*inv3);
      v = g_v4[ni1*32+lane];
      v.w=(v.x*shB.y+v.y*shB.z+v.z*shB.w)*inv3; vdb[lane]=v;
      v = g_v4[nj1*32+lane];
      v.w=(v.x*shB.y+v.y*shB.z+v.z*shB.w)*inv3; vdb[32+lane]=v;
      ex=rb[64+3*lane]; ey=rb[65+3*lane]; ez=rb[66+3*lane];
      vdb[64+lane]=make_float4(ex,ey,ez,(ex*shB.y+ey*shB.z+ez*shB.w)*inv3);
    }
    __syncwarp();

    float a0=0.f,a1=0.f,ag=0.f,at=0.f;
    float d0=0.f,d1=0.f,dg=0.f,dt=0.f;
    #pragma unroll 4
    for (int u=0;u<192;u+=4){
      float4 x = *(float4*)(s1a+u);
      float4 y = *(float4*)(s1b+u);
      float4 w;
      w=F1[(u  )*32+lane]; a0+=x.x*w.x; a1+=x.x*w.y; ag+=x.x*w.z; at+=x.x*w.w;
                           d0+=y.x*w.x; d1+=y.x*w.y; dg+=y.x*w.z; dt+=y.x*w.w;
      w=F1[(u+1)*32+lane]; a0+=x.y*w.x; a1+=x.y*w.y; ag+=x.y*w.z; at+=x.y*w.w;
                           d0+=y.y*w.x; d1+=y.y*w.y; dg+=y.y*w.z; dt+=y.y*w.w;
      w=F1[(u+2)*32+lane]; a0+=x.z*w.x; a1+=x.z*w.y; ag+=x.z*w.z; at+=x.z*w.w;
                           d0+=y.z*w.x; d1+=y.z*w.y; dg+=y.z*w.z; dt+=y.z*w.w;
      w=F1[(u+3)*32+lane]; a0+=x.w*w.x; a1+=x.w*w.y; ag+=x.w*w.z; at+=x.w*w.w;
                           d0+=y.w*w.x; d1+=y.w*w.y; dg+=y.w*w.z; dt+=y.w*w.w;
    }
    float b0=0.f,b1=0.f,bg=0.f,r0=0.f,r1=0.f,r2=0.f;
    float c0=0.f,c1=0.f,cg=0.f,q0=0.f,q1=0.f,q2=0.f;
    #pragma unroll 4
    for (int u=0;u<96;u++){
      float4 v = vda[u];
      float4 t = vdb[u];
      float4 w = F2[u*32+lane];
      b0+=v.w*w.x; b1+=v.w*w.y; bg+=v.w*w.z;
      r0+=v.x*w.w; r1+=v.y*w.w; r2+=v.z*w.w;
      c0+=t.w*w.x; c1+=t.w*w.y; cg+=t.w*w.z;
      q0+=t.x*w.w; q1+=t.y*w.w; q2+=t.z*w.w;
    }
    // edge A
    {
      float zs0=(shA.x*a0+b0)*invfan, zs1=(shA.x*a1+b1)*invfan;
      float zg =(shA.x*ag+bg)*invfan;
      const float* wm = g_wmlp + (long long)e0*96;
      float2 wm01 = *(const float2*)(wm+2*lane);
      float wmv = wm[64+lane];
      zs0 = zs0*sig_(zs0)*wm01.x;
      zs1 = zs1*sig_(zs1)*wm01.y;
      float gv = sig_(zg)*wmv*invfan;
      atomicAdd(&g_accs[ni0*64+2*lane],   zs0);
      atomicAdd(&g_accs[ni0*64+2*lane+1], zs1);
      atomicAdd(&g_accv[ni0*96+3*lane],   (at*shA.y + r0*shA.x)*gv);
      atomicAdd(&g_accv[ni0*96+3*lane+1], (at*shA.z + r1*shA.x)*gv);
      atomicAdd(&g_accv[ni0*96+3*lane+2], (at*shA.w + r2*shA.x)*gv);
    }
    // edge B
    {
      float zs0=(shB.x*d0+c0)*invfan, zs1=(shB.x*d1+c1)*invfan;
      float zg =(shB.x*dg+cg)*invfan;
      const float* wm = g_wmlp + (long long)e1*96;
      float2 wm01 = *(const float2*)(wm+2*lane);
      float wmv = wm[64+lane];
      zs0 = zs0*sig_(zs0)*wm01.x;
      zs1 = zs1*sig_(zs1)*wm01.y;
      float gv = sig_(zg)*wmv*invfan;
      atomicAdd(&g_accs[ni1*64+2*lane],   zs0);
      atomicAdd(&g_accs[ni1*64+2*lane+1], zs1);
      atomicAdd(&g_accv[ni1*96+3*lane],   (dt*shB.y + q0*shB.x)*gv);
      atomicAdd(&g_accv[ni1*96+3*lane+1], (dt*shB.z + q1*shB.x)*gv);
      atomicAdd(&g_accv[ni1*96+3*lane+2], (dt*shB.w + q2*shB.x)*gv);
    }
    __syncwarp();
  }
}

// ---------------- node post: pp projection + self-connection + group moments ----------------
__global__ void __launch_bounds__(512) k_node_post(const int* __restrict__ batch,
   const float* __restrict__ ppWs, const float* __restrict__ ppbs,
   const float* __restrict__ ppWv){
  extern __shared__ float sm[];
  float2* WsS = (float2*)sm;   // 4096 f
  float* WvS = sm+4096;        // 1024 f
  float* bsS = sm+5120;        // 64
  float* stage = sm+5184;      // per-warp 192
  for (int i=threadIdx.x;i<4096;i+=blockDim.x) sm[i]=ppWs[i];
  for (int i=threadIdx.x;i<1024;i+=blockDim.x) WvS[i]=ppWv[i];
  for (int i=threadIdx.x;i<64;i+=blockDim.x) bsS[i]=ppbs[i];
  __syncthreads();
  int warp=threadIdx.x>>5, lane=threadIdx.x&31, wpb=blockDim.x>>5;
  float*  sS  = stage + warp*192;
  float4* vS  = (float4*)(sS+64);
  for (int n=blockIdx.x*wpb+warp; n<NN; n+=gridDim.x*wpb){
    sS[lane]=g_accs[n*64+lane]; sS[32+lane]=g_accs[n*64+32+lane];
    vS[lane]=make_float4(g_accv[n*96+3*lane],g_accv[n*96+3*lane+1],g_accv[n*96+3*lane+2],0.f);
    __syncwarp();
    float a0=0.f,a1=0.f;
    #pragma unroll 4
    for (int u=0;u<64;u++){
      float x=sS[u]; float2 w=WsS[u*32+lane];
      a0+=x*w.x; a1+=x*w.y;
    }
    float ns0 = a0*0.125f + bsS[2*lane]   + g_scs[n*64+2*lane];
    float ns1 = a1*0.125f + bsS[2*lane+1] + g_scs[n*64+2*lane+1];
    g_ns[n*64+2*lane]=ns0; g_ns[n*64+2*lane+1]=ns1;
    float vx=0.f,vy=0.f,vz=0.f;
    #pragma unroll 4
    for (int u=0;u<32;u++){
      float4 x=vS[u]; float w=WvS[u*32+lane];
      vx+=x.x*w; vy+=x.y*w; vz+=x.z*w;
    }
    float nv0 = vx*0.17677670f + g_scv[n*96+3*lane];
    float nv1 = vy*0.17677670f + g_scv[n*96+3*lane+1];
    float nv2 = vz*0.17677670f + g_scv[n*96+3*lane+2];
    g_nv[n*96+3*lane]=nv0; g_nv[n*96+3*lane+1]=nv1; g_nv[n*96+3*lane+2]=nv2;
    float m = ns0+ns1;
    float q = ns0*ns0+ns1*ns1;
    float pw = nv0*nv0+nv1*nv1+nv2*nv2;
    #pragma unroll
    for (int off=16;off>0;off>>=1){
      m += __shfl_down_sync(0xffffffffu, m, off);
      q += __shfl_down_sync(0xffffffffu, q, off);
      pw += __shfl_down_sync(0xffffffffu, pw, off);
    }
    if (lane==0){
      int g = batch[n];
      atomicAdd(&g_gstat[g],        m*(1.f/64.f));
      atomicAdd(&g_gstat[NG_+g],    q*(1.f/64.f));
      atomicAdd(&g_gstat[2*NG_+g],  pw*(1.f/96.f));
      atomicAdd(&g_gstat[3*NG_+g],  1.f);
    }
    __syncwarp();
  }
}

// ---------------- group finalize ----------------
__global__ void k_groups(){
  int t = threadIdx.x;
  if (t < NG_){
    float c  = fmaxf(g_gstat[3*NG_+t], 1.f);
    float mu = g_gstat[t]/c;
    float vs = g_gstat[NG_+t]/c - mu*mu;
    float vv = g_gstat[2*NG_+t]/c;
    g_gout[t]       = mu;
    g_gout[NG_+t]   = rsqrtf(vs+1e-5f);
    g_gout[2*NG_+t] = rsqrtf(vv+1e-5f);
  }
}

// ---------------- apply norm + residual ----------------
__global__ void k_out(const float* __restrict__ nf, const int* __restrict__ batch,
   const float* __restrict__ lnws, const float* __restrict__ lnbs,
   const float* __restrict__ lnwv, float* __restrict__ out){
  int i = blockIdx.x*blockDim.x+threadIdx.x;
  if (i >= NN*160) return;
  int n = i/160, c = i - n*160;
  int g = batch[n];
  float base = nf[i];
  float o;
  if (c < 64){
    float x = (g_ns[n*64+c] - g_gout[g]) * g_gout[NG_+g];
    o = base + x*lnws[c] + lnbs[c];
  } else {
    int cc = c-64;
    o = base + g_nv[n*96+cc]*g_gout[2*NG_+g]*lnwv[cc/3];
  }
  out[i]=o;
}

// ---------------- launcher ----------------
extern "C" void kernel_launch(void* const* d_in, const int* in_sizes, int n_in,
                              void* d_out, int out_size){
  const float* nf   =(const float*)d_in[0];
  const float* oh   =(const float*)d_in[1];
  const float* esh  =(const float*)d_in[2];
  const float* efea =(const float*)d_in[3];
  const float* ele  =(const float*)d_in[4];
  const int*   eidx =(const int*)d_in[5];
  const int*   batch=(const int*)d_in[6];
  const float* lpWs =(const float*)d_in[7];
  const float* lpbs =(const float*)d_in[8];
  const float* lpWv =(const float*)d_in[9];
  const float* ppWs =(const float*)d_in[10];
  const float* ppbs =(const float*)d_in[11];
  const float* ppWv =(const float*)d_in[12];
  const float* scWs =(const float*)d_in[13];
  const float* scWv =(const float*)d_in[14];
  const float* Wss0 =(const float*)d_in[15];
  const float* Wvv0 =(const float*)d_in[16];
  const float* Wssg =(const float*)d_in[17];
  const float* Wvvg =(const float*)d_in[18];
  const float* Wsv1 =(const float*)d_in[19];
  const float* Wvs1 =(const float*)d_in[20];
  const float* fcW1 =(const float*)d_in[21];
  const float* fcb1 =(const float*)d_in[22];
  const float* fcW2 =(const float*)d_in[23];
  const float* fcb2 =(const float*)d_in[24];
  const float* fcW3 =(const float*)d_in[25];
  const float* fcb3 =(const float*)d_in[26];
  const float* lnws =(const float*)d_in[27];
  const float* lnbs =(const float*)d_in[28];
  const float* lnwv =(const float*)d_in[29];
  float* out = (float*)d_out;

  const int SM_PRE  = (25664 + 16*192)*4;   // 114944
  const int SM_MLP  = (20704 + 16*512)*4;   // 115584
  const int SM_EDGE = (36864 + 16*1152)*4;  // 221184
  const int SM_POST = (5184  + 16*192)*4;   // 33024
  cudaFuncSetAttribute(k_node_pre,  cudaFuncAttributeMaxDynamicSharedMemorySize, SM_PRE);
  cudaFuncSetAttribute(k_mlp,       cudaFuncAttributeMaxDynamicSharedMemorySize, SM_MLP);
  cudaFuncSetAttribute(k_edge,      cudaFuncAttributeMaxDynamicSharedMemorySize, SM_EDGE);
  cudaFuncSetAttribute(k_node_post, cudaFuncAttributeMaxDynamicSharedMemorySize, SM_POST);

  k_zero<<<(NN*160 + 4*NG_ + 255)/256, 256>>>();
  k_node_pre<<<148, 512, SM_PRE>>>(nf, oh, lpWs, lpbs, lpWv, scWs, scWv);
  k_mlp<<<1184, 512, SM_MLP>>>(ele, fcW1, fcb1, fcW2, fcb2, fcW3, fcb3);
  k_edge<<<1184, 512, SM_EDGE>>>(eidx, esh, efea, Wss0, Wvv0, Wssg, Wvvg, Wsv1, Wvs1);
  k_node_post<<<148, 512, SM_POST>>>(batch, ppWs, ppbs, ppWv);
  k_groups<<<1, 32>>>();
  k_out<<<(NN*160 + 255)/256, 256>>>(nf, batch, lnws, lnbs, lnwv, out);
}

// round 3
// speedup vs baseline: 1.2489x; 1.2489x over previous
#include <cuda_runtime.h>

#define NN 10000
#define EE 320000
#define NG_ 16

// ---------------- scratch (static device memory; no allocations) ----------------
__device__ float  g_s[NN*64];
__device__ float4 g_v4[NN*32];
__device__ float  g_scs[NN*64];
__device__ float  g_scv[NN*96];
__device__ float  g_accs[NN*64];
__device__ float  g_accv[NN*96];
__device__ float  g_ns[NN*64];
__device__ float  g_nv[NN*96];
__device__ float  g_wmlp[(long long)EE*96];
__device__ float  g_gstat[4*NG_];
__device__ float  g_gout[3*NG_];

__device__ __forceinline__ float sig_(float x){ return 1.f/(1.f+__expf(-x)); }

// ---- f32x2 packed math helpers (sm_103a FFMA2 via PTX) ----
__device__ __forceinline__ unsigned long long pk2(float x){
  unsigned long long r; asm("mov.b64 %0, {%1, %1};" : "=l"(r) : "f"(x)); return r; }
__device__ __forceinline__ unsigned long long pkab(float a, float b){
  unsigned long long r; asm("mov.b64 %0, {%1, %2};" : "=l"(r) : "f"(a), "f"(b)); return r; }
__device__ __forceinline__ void up2(unsigned long long v, float &a, float &b){
  asm("mov.b64 {%0, %1}, %2;" : "=f"(a), "=f"(b) : "l"(v)); }
__device__ __forceinline__ void fma2(unsigned long long &d, unsigned long long a, unsigned long long b){
  asm("fma.rn.f32x2 %0, %1, %2, %3;" : "=l"(d) : "l"(a), "l"(b), "l"(d)); }

// ---------------- zero accumulators ----------------
__global__ void k_zero(){
  int i = blockIdx.x*blockDim.x + threadIdx.x;
  if (i < NN*64) g_accs[i] = 0.f;
  int j = i - NN*64;
  if (j >= 0 && j < NN*96) g_accv[j] = 0.f;
  int k = i - NN*160;
  if (k >= 0 && k < 4*NG_) g_gstat[k] = 0.f;
}

// ---------------- node pre ----------------
__global__ void __launch_bounds__(512) k_node_pre(const float* __restrict__ nf,
                           const float* __restrict__ oh,
                           const float* __restrict__ lpWs, const float* __restrict__ lpbs,
                           const float* __restrict__ lpWv,
                           const float* __restrict__ scWs, const float* __restrict__ scWv){
  extern __shared__ float sm[];
  float2* WsS  = (float2*)sm;
  float*  WvS  = sm + 4096;
  float2* sWsS = (float2*)(sm + 5120);
  float*  sWvS = sm + 21504;
  float*  bsS  = sm + 25600;
  float*  stage= sm + 25664;

  for (int i=threadIdx.x;i<4096;i+=blockDim.x) sm[i]=lpWs[i];
  for (int i=threadIdx.x;i<1024;i+=blockDim.x) WvS[i]=lpWv[i];
  for (int i=threadIdx.x;i<16384;i+=blockDim.x) sm[5120+i]=scWs[i];
  for (int i=threadIdx.x;i<4096;i+=blockDim.x) sWvS[i]=scWv[i];
  for (int i=threadIdx.x;i<64;i+=blockDim.x) bsS[i]=lpbs[i];
  __syncthreads();

  int warp = threadIdx.x>>5, lane = threadIdx.x&31, wpb = blockDim.x>>5;
  float*  sS  = stage + warp*192;
  float4* vS  = (float4*)(sS + 64);

  for (int n = blockIdx.x*wpb + warp; n < NN; n += gridDim.x*wpb){
    const float* row = nf + n*160;
    sS[lane] = row[lane]; sS[32+lane] = row[32+lane];
    vS[lane] = make_float4(row[64+3*lane], row[65+3*lane], row[66+3*lane], 0.f);
    const float* o4 = oh + n*4;
    int sp = (o4[1]>0.5f)?1:((o4[2]>0.5f)?2:((o4[3]>0.5f)?3:0));
    __syncwarp();

    float a0=0.f,a1=0.f,c0=0.f,c1=0.f;
    #pragma unroll 4
    for (int u=0;u<64;u++){
      float x = sS[u];
      float2 w  = WsS[u*32+lane];
      float2 w2 = sWsS[(u*4+sp)*32+lane];
      a0+=x*w.x; a1+=x*w.y; c0+=x*w2.x; c1+=x*w2.y;
    }
    g_s[n*64+2*lane]   = a0*0.125f + bsS[2*lane];
    g_s[n*64+2*lane+1] = a1*0.125f + bsS[2*lane+1];
    g_scs[n*64+2*lane]   = c0*0.0625f;
    g_scs[n*64+2*lane+1] = c1*0.0625f;

    float vx=0.f,vy=0.f,vz=0.f,cx=0.f,cy=0.f,cz=0.f;
    #pragma unroll 4
    for (int u=0;u<32;u++){
      float4 x = vS[u];
      float w  = WvS[u*32+lane];
      float w2 = sWvS[(u*4+sp)*32+lane];
      vx+=x.x*w;  vy+=x.y*w;  vz+=x.z*w;
      cx+=x.x*w2; cy+=x.y*w2; cz+=x.z*w2;
    }
    g_v4[n*32+lane] = make_float4(vx*0.17677670f, vy*0.17677670f, vz*0.17677670f, 0.f);
    g_scv[n*96+3*lane]   = cx*0.08838835f;
    g_scv[n*96+3*lane+1] = cy*0.08838835f;
    g_scv[n*96+3*lane+2] = cz*0.08838835f;
    __syncwarp();
  }
}

// ---------------- per-edge MLP (128->64->64->96), 8 edges/warp, f32x2 ----------------
__global__ void __launch_bounds__(512) k_mlp(const float* __restrict__ ele,
   const float* __restrict__ W1, const float* __restrict__ b1,
   const float* __restrict__ W2, const float* __restrict__ b2,
   const float* __restrict__ W3, const float* __restrict__ b3){
  extern __shared__ float sm[];
  // W1S: float2[128*32]   [0,8192)
  // W2S: float2[64*32]    [8192,12288)
  // W3p: float2[64*32]    [12288,16384)   outputs (l, 32+l)
  // W3s: float [64*32]    [16384,18432)   output  64+l
  // b1S @18432, b2S @18496, b3S @18560(96), stage @18656 (per warp 2048)
  float* b1S = sm+18432; float* b2S = sm+18496; float* b3S = sm+18560;
  float* stage = sm+18656;

  for (int i=threadIdx.x;i<8192;i+=blockDim.x) sm[i]=W1[i];
  for (int i=threadIdx.x;i<4096;i+=blockDim.x) sm[8192+i]=W2[i];
  for (int i=threadIdx.x;i<2048;i+=blockDim.x){
    int j=i>>5, l=i&31;
    ((float2*)(sm+12288))[i] = make_float2(W3[j*96+l], W3[j*96+32+l]);
    sm[16384+i] = W3[j*96+64+l];
  }
  for (int i=threadIdx.x;i<64;i+=blockDim.x){ b1S[i]=b1[i]; b2S[i]=b2[i]; }
  for (int i=threadIdx.x;i<96;i+=blockDim.x) b3S[i]=b3[i];
  __syncthreads();

  int warp=threadIdx.x>>5, lane=threadIdx.x&31, wpb=blockDim.x>>5;
  float* st = stage + warp*2048;   // 8 edges x 256 (e:128, h:64, g:64)

  unsigned long long bias1 = pkab(b1S[2*lane], b1S[2*lane+1]);
  unsigned long long bias2 = pkab(b2S[2*lane], b2S[2*lane+1]);
  unsigned long long bias3 = pkab(b3S[lane],   b3S[32+lane]);
  float bias3s = b3S[64+lane];

  const int octs = EE/8;
  for (int p = blockIdx.x*wpb+warp; p<octs; p+=gridDim.x*wpb){
    long long e0 = 8LL*p;
    #pragma unroll
    for (int k=0;k<8;k++){
      const float* r = ele + (e0+k)*128;
      float* eE = st + k*256;
      #pragma unroll
      for (int c=0;c<4;c++) eE[c*32+lane]=r[c*32+lane];
    }
    __syncwarp();

    // ---- layer 1: 128 -> 64 ----
    unsigned long long acc[8];
    #pragma unroll
    for (int k=0;k<8;k++) acc[k]=bias1;
    #pragma unroll 2
    for (int j=0;j<128;j+=4){
      unsigned long long w0=*(unsigned long long*)(sm+ (j  )*64 + 2*lane);
      unsigned long long w1=*(unsigned long long*)(sm+ (j+1)*64 + 2*lane);
      unsigned long long w2=*(unsigned long long*)(sm+ (j+2)*64 + 2*lane);
      unsigned long long w3=*(unsigned long long*)(sm+ (j+3)*64 + 2*lane);
      #pragma unroll
      for (int k=0;k<8;k++){
        float4 x = *(float4*)(st + k*256 + j);
        fma2(acc[k], pk2(x.x), w0);
        fma2(acc[k], pk2(x.y), w1);
        fma2(acc[k], pk2(x.z), w2);
        fma2(acc[k], pk2(x.w), w3);
      }
    }
    #pragma unroll
    for (int k=0;k<8;k++){
      float a0,a1; up2(acc[k],a0,a1);
      float* hE = st + k*256 + 128;
      hE[2*lane]=a0*sig_(a0); hE[2*lane+1]=a1*sig_(a1);
    }
    __syncwarp();

    // ---- layer 2: 64 -> 64 ----
    #pragma unroll
    for (int k=0;k<8;k++) acc[k]=bias2;
    #pragma unroll 2
    for (int j=0;j<64;j+=4){
      unsigned long long w0=*(unsigned long long*)(sm+8192+(j  )*64 + 2*lane);
      unsigned long long w1=*(unsigned long long*)(sm+8192+(j+1)*64 + 2*lane);
      unsigned long long w2=*(unsigned long long*)(sm+8192+(j+2)*64 + 2*lane);
      unsigned long long w3=*(unsigned long long*)(sm+8192+(j+3)*64 + 2*lane);
      #pragma unroll
      for (int k=0;k<8;k++){
        float4 x = *(float4*)(st + k*256 + 128 + j);
        fma2(acc[k], pk2(x.x), w0);
        fma2(acc[k], pk2(x.y), w1);
        fma2(acc[k], pk2(x.z), w2);
        fma2(acc[k], pk2(x.w), w3);
      }
    }
    #pragma unroll
    for (int k=0;k<8;k++){
      float a0,a1; up2(acc[k],a0,a1);
      float* gE = st + k*256 + 192;
      gE[2*lane]=a0*sig_(a0); gE[2*lane+1]=a1*sig_(a1);
    }
    __syncwarp();

    // ---- layer 3: 64 -> 96 ----
    unsigned long long c01[8]; float c2[8];
    #pragma unroll
    for (int k=0;k<8;k++){ c01[k]=bias3; c2[k]=bias3s; }
    #pragma unroll 2
    for (int j=0;j<64;j+=4){
      unsigned long long p0=*(unsigned long long*)(sm+12288+(j  )*64 + 2*lane);
      unsigned long long p1=*(unsigned long long*)(sm+12288+(j+1)*64 + 2*lane);
      unsigned long long p2=*(unsigned long long*)(sm+12288+(j+2)*64 + 2*lane);
      unsigned long long p3=*(unsigned long long*)(sm+12288+(j+3)*64 + 2*lane);
      float s0=sm[16384+(j  )*32+lane];
      float s1=sm[16384+(j+1)*32+lane];
      float s2=sm[16384+(j+2)*32+lane];
      float s3=sm[16384+(j+3)*32+lane];
      #pragma unroll
      for (int k=0;k<8;k++){
        float4 x = *(float4*)(st + k*256 + 192 + j);
        fma2(c01[k], pk2(x.x), p0); c2[k]+=x.x*s0;
        fma2(c01[k], pk2(x.y), p1); c2[k]+=x.y*s1;
        fma2(c01[k], pk2(x.z), p2); c2[k]+=x.z*s2;
        fma2(c01[k], pk2(x.w), p3); c2[k]+=x.w*s3;
      }
    }
    #pragma unroll
    for (int k=0;k<8;k++){
      float a,b; up2(c01[k],a,b);
      float* wo = g_wmlp + (e0+k)*96;
      wo[lane]=a; wo[32+lane]=b; wo[64+lane]=c2[k];
    }
    __syncwarp();
  }
}

// ---------------- edge interaction + scatter, 4 edges/warp, f32x2 ----------------
__global__ void __launch_bounds__(256) k_edge(const int* __restrict__ eidx,
   const float* __restrict__ esh, const float* __restrict__ efea,
   const float* __restrict__ Wss0, const float* __restrict__ Wvv0,
   const float* __restrict__ Wssg, const float* __restrict__ Wvvg,
   const float* __restrict__ Wsv1, const float* __restrict__ Wvs1){
  extern __shared__ float sm[];
  float4* F1 = (float4*)sm;            // 192x32 f4: (ss0[2l],ss0[2l+1],ssg[l],sv1[l])
  float4* F2 = (float4*)(sm+24576);    // 96x32  f4: (vv0[2l],vv0[2l+1],vvg[l],vs1[l])
  float* stage = sm + 36864;           // per warp 2320 f

  for (int i=threadIdx.x;i<6144;i+=blockDim.x){
    int u=i>>5, l=i&31;
    F1[i]=make_float4(Wss0[u*64+2*l], Wss0[u*64+2*l+1], Wssg[u*32+l], Wsv1[u*32+l]);
  }
  for (int i=threadIdx.x;i<3072;i+=blockDim.x){
    int u=i>>5, l=i&31;
    F2[i]=make_float4(Wvv0[u*64+2*l], Wvv0[u*64+2*l+1], Wvvg[u*32+l], Wvs1[u*32+l]);
  }
  __syncthreads();

  int warp=threadIdx.x>>5, lane=threadIdx.x&31, wpb=blockDim.x>>5;
  float*  st  = stage + warp*2320;
  float*  s1  = st;                    // 4 x 192
  float4* vdd = (float4*)(st+768);     // 4 x 96 f4
  float4* shS = (float4*)(st+2304);    // 4 f4
  const float inv3 = 0.57735027f, invfan = 0.058925565f;
  const int quads = EE/4;

  for (int p = blockIdx.x*wpb+warp; p<quads; p+=gridDim.x*wpb){
    int ni[4];
    #pragma unroll
    for (int k=0;k<4;k++){
      int e = 4*p+k;
      ni[k]=eidx[e]; int nj=eidx[EE+e];
      float4 sh = *(const float4*)(esh + (long long)e*4);
      if (lane==0) shS[k]=sh;
      const float* r = efea + (long long)e*160;
      float* s1k = s1 + k*192;
      s1k[lane]     = g_s[ni[k]*64+lane];
      s1k[32+lane]  = g_s[ni[k]*64+32+lane];
      s1k[64+lane]  = g_s[nj*64+lane];
      s1k[96+lane]  = g_s[nj*64+32+lane];
      s1k[128+lane] = r[lane];
      s1k[160+lane] = r[32+lane];
      float4* vk = vdd + k*96;
      float4 v = g_v4[ni[k]*32+lane];
      v.w=(v.x*sh.y+v.y*sh.z+v.z*sh.w)*inv3; vk[lane]=v;
      v = g_v4[nj*32+lane];
      v.w=(v.x*sh.y+v.y*sh.z+v.z*sh.w)*inv3; vk[32+lane]=v;
      float ex=r[64+3*lane], ey=r[65+3*lane], ez=r[66+3*lane];
      vk[64+lane]=make_float4(ex,ey,ez,(ex*sh.y+ey*sh.z+ez*sh.w)*inv3);
    }
    __syncwarp();

    // ---- F1: zs(2 outs), zg, t per lane, 4 edges, packed (a0,a1) & (ag,at) ----
    unsigned long long a01[4], agt[4];
    #pragma unroll
    for (int k=0;k<4;k++){ a01[k]=0ull; agt[k]=0ull; }
    #pragma unroll 2
    for (int u=0;u<192;u+=4){
      float x0[4], x1[4], x2[4], x3[4];
      *(float4*)x0 = *(float4*)(s1 + 0*192 + u);
      *(float4*)x1 = *(float4*)(s1 + 1*192 + u);
      *(float4*)x2 = *(float4*)(s1 + 2*192 + u);
      *(float4*)x3 = *(float4*)(s1 + 3*192 + u);
      #pragma unroll
      for (int sub=0;sub<4;sub++){
        ulonglong2 w = *(ulonglong2*)&F1[(u+sub)*32+lane];
        unsigned long long xx;
        xx = pk2(x0[sub]); fma2(a01[0], xx, w.x); fma2(agt[0], xx, w.y);
        xx = pk2(x1[sub]); fma2(a01[1], xx, w.x); fma2(agt[1], xx, w.y);
        xx = pk2(x2[sub]); fma2(a01[2], xx, w.x); fma2(agt[2], xx, w.y);
        xx = pk2(x3[sub]); fma2(a01[3], xx, w.x); fma2(agt[3], xx, w.y);
      }
    }

    // ---- F2: (b0,b1), (r0,r1), (bg,r2) per lane, 4 edges ----
    unsigned long long b01[4], r01[4], gz2[4];
    #pragma unroll
    for (int k=0;k<4;k++){ b01[k]=0ull; r01[k]=0ull; gz2[k]=0ull; }
    #pragma unroll 4
    for (int u=0;u<96;u++){
      ulonglong2 w = *(ulonglong2*)&F2[u*32+lane];
      float wz,ww; up2(w.y, wz, ww);
      unsigned long long www = pk2(ww);
      #pragma unroll
      for (int k=0;k<4;k++){
        float4 v = vdd[k*96+u];
        fma2(b01[k], pk2(v.w), w.x);
        fma2(r01[k], pkab(v.x,v.y), www);
        fma2(gz2[k], pkab(v.w,v.z), w.y);   // (dd*wz, vz*ww) = (bg, r2)
      }
    }

    // ---- epilogue + scatter ----
    #pragma unroll
    for (int k=0;k<4;k++){
      float a0,a1,ag,at,b0,b1,r0,r1,bg,r2;
      up2(a01[k],a0,a1); up2(agt[k],ag,at);
      up2(b01[k],b0,b1); up2(r01[k],r0,r1); up2(gz2[k],bg,r2);
      float4 sh = shS[k];
      float zs0=(sh.x*a0+b0)*invfan, zs1=(sh.x*a1+b1)*invfan;
      float zg =(sh.x*ag+bg)*invfan;
      long long e = 4LL*p+k;
      const float* wm = g_wmlp + e*96;
      float2 wm01 = *(const float2*)(wm+2*lane);
      float wmv = wm[64+lane];
      zs0 = zs0*sig_(zs0)*wm01.x;
      zs1 = zs1*sig_(zs1)*wm01.y;
      float gv = sig_(zg)*wmv*invfan;
      int n = ni[k];
      atomicAdd(&g_accs[n*64+2*lane],   zs0);
      atomicAdd(&g_accs[n*64+2*lane+1], zs1);
      atomicAdd(&g_accv[n*96+3*lane],   (at*sh.y + r0*sh.x)*gv);
      atomicAdd(&g_accv[n*96+3*lane+1], (at*sh.z + r1*sh.x)*gv);
      atomicAdd(&g_accv[n*96+3*lane+2], (at*sh.w + r2*sh.x)*gv);
    }
    __syncwarp();
  }
}

// ---------------- node post ----------------
__global__ void __launch_bounds__(512) k_node_post(const int* __restrict__ batch,
   const float* __restrict__ ppWs, const float* __restrict__ ppbs,
   const float* __restrict__ ppWv){
  extern __shared__ float sm[];
  float2* WsS = (float2*)sm;
  float* WvS = sm+4096;
  float* bsS = sm+5120;
  float* stage = sm+5184;
  for (int i=threadIdx.x;i<4096;i+=blockDim.x) sm[i]=ppWs[i];
  for (int i=threadIdx.x;i<1024;i+=blockDim.x) WvS[i]=ppWv[i];
  for (int i=threadIdx.x;i<64;i+=blockDim.x) bsS[i]=ppbs[i];
  __syncthreads();
  int warp=threadIdx.x>>5, lane=threadIdx.x&31, wpb=blockDim.x>>5;
  float*  sS  = stage + warp*192;
  float4* vS  = (float4*)(sS+64);
  for (int n=blockIdx.x*wpb+warp; n<NN; n+=gridDim.x*wpb){
    sS[lane]=g_accs[n*64+lane]; sS[32+lane]=g_accs[n*64+32+lane];
    vS[lane]=make_float4(g_accv[n*96+3*lane],g_accv[n*96+3*lane+1],g_accv[n*96+3*lane+2],0.f);
    __syncwarp();
    float a0=0.f,a1=0.f;
    #pragma unroll 4
    for (int u=0;u<64;u++){
      float x=sS[u]; float2 w=WsS[u*32+lane];
      a0+=x*w.x; a1+=x*w.y;
    }
    float ns0 = a0*0.125f + bsS[2*lane]   + g_scs[n*64+2*lane];
    float ns1 = a1*0.125f + bsS[2*lane+1] + g_scs[n*64+2*lane+1];
    g_ns[n*64+2*lane]=ns0; g_ns[n*64+2*lane+1]=ns1;
    float vx=0.f,vy=0.f,vz=0.f;
    #pragma unroll 4
    for (int u=0;u<32;u++){
      float4 x=vS[u]; float w=WvS[u*32+lane];
      vx+=x.x*w; vy+=x.y*w; vz+=x.z*w;
    }
    float nv0 = vx*0.17677670f + g_scv[n*96+3*lane];
    float nv1 = vy*0.17677670f + g_scv[n*96+3*lane+1];
    float nv2 = vz*0.17677670f + g_scv[n*96+3*lane+2];
    g_nv[n*96+3*lane]=nv0; g_nv[n*96+3*lane+1]=nv1; g_nv[n*96+3*lane+2]=nv2;
    float m = ns0+ns1;
    float q = ns0*ns0+ns1*ns1;
    float pw = nv0*nv0+nv1*nv1+nv2*nv2;
    #pragma unroll
    for (int off=16;off>0;off>>=1){
      m += __shfl_down_sync(0xffffffffu, m, off);
      q += __shfl_down_sync(0xffffffffu, q, off);
      pw += __shfl_down_sync(0xffffffffu, pw, off);
    }
    if (lane==0){
      int g = batch[n];
      atomicAdd(&g_gstat[g],        m*(1.f/64.f));
      atomicAdd(&g_gstat[NG_+g],    q*(1.f/64.f));
      atomicAdd(&g_gstat[2*NG_+g],  pw*(1.f/96.f));
      atomicAdd(&g_gstat[3*NG_+g],  1.f);
    }
    __syncwarp();
  }
}

// ---------------- group finalize ----------------
__global__ void k_groups(){
  int t = threadIdx.x;
  if (t < NG_){
    float c  = fmaxf(g_gstat[3*NG_+t], 1.f);
    float mu = g_gstat[t]/c;
    float vs = g_gstat[NG_+t]/c - mu*mu;
    float vv = g_gstat[2*NG_+t]/c;
    g_gout[t]       = mu;
    g_gout[NG_+t]   = rsqrtf(vs+1e-5f);
    g_gout[2*NG_+t] = rsqrtf(vv+1e-5f);
  }
}

// ---------------- apply norm + residual ----------------
__global__ void k_out(const float* __restrict__ nf, const int* __restrict__ batch,
   const float* __restrict__ lnws, const float* __restrict__ lnbs,
   const float* __restrict__ lnwv, float* __restrict__ out){
  int i = blockIdx.x*blockDim.x+threadIdx.x;
  if (i >= NN*160) return;
  int n = i/160, c = i - n*160;
  int g = batch[n];
  float base = nf[i];
  float o;
  if (c < 64){
    float x = (g_ns[n*64+c] - g_gout[g]) * g_gout[NG_+g];
    o = base + x*lnws[c] + lnbs[c];
  } else {
    int cc = c-64;
    o = base + g_nv[n*96+cc]*g_gout[2*NG_+g]*lnwv[cc/3];
  }
  out[i]=o;
}

// ---------------- launcher ----------------
extern "C" void kernel_launch(void* const* d_in, const int* in_sizes, int n_in,
                              void* d_out, int out_size){
  const float* nf   =(const float*)d_in[0];
  const float* oh   =(const float*)d_in[1];
  const float* esh  =(const float*)d_in[2];
  const float* efea =(const float*)d_in[3];
  const float* ele  =(const float*)d_in[4];
  const int*   eidx =(const int*)d_in[5];
  const int*   batch=(const int*)d_in[6];
  const float* lpWs =(const float*)d_in[7];
  const float* lpbs =(const float*)d_in[8];
  const float* lpWv =(const float*)d_in[9];
  const float* ppWs =(const float*)d_in[10];
  const float* ppbs =(const float*)d_in[11];
  const float* ppWv =(const float*)d_in[12];
  const float* scWs =(const float*)d_in[13];
  const float* scWv =(const float*)d_in[14];
  const float* Wss0 =(const float*)d_in[15];
  const float* Wvv0 =(const float*)d_in[16];
  const float* Wssg =(const float*)d_in[17];
  const float* Wvvg =(const float*)d_in[18];
  const float* Wsv1 =(const float*)d_in[19];
  const float* Wvs1 =(const float*)d_in[20];
  const float* fcW1 =(const float*)d_in[21];
  const float* fcb1 =(const float*)d_in[22];
  const float* fcW2 =(const float*)d_in[23];
  const float* fcb2 =(const float*)d_in[24];
  const float* fcW3 =(const float*)d_in[25];
  const float* fcb3 =(const float*)d_in[26];
  const float* lnws =(const float*)d_in[27];
  const float* lnbs =(const float*)d_in[28];
  const float* lnwv =(const float*)d_in[29];
  float* out = (float*)d_out;

  const int SM_PRE  = (25664 + 16*192)*4;   // 114944
  const int SM_MLP  = (18656 + 16*2048)*4;  // 205696
  const int SM_EDGE = (36864 + 8*2320)*4;   // 221696
  const int SM_POST = (5184  + 16*192)*4;   // 33024
  cudaFuncSetAttribute(k_node_pre,  cudaFuncAttributeMaxDynamicSharedMemorySize, SM_PRE);
  cudaFuncSetAttribute(k_mlp,       cudaFuncAttributeMaxDynamicSharedMemorySize, SM_MLP);
  cudaFuncSetAttribute(k_edge,      cudaFuncAttributeMaxDynamicSharedMemorySize, SM_EDGE);
  cudaFuncSetAttribute(k_node_post, cudaFuncAttributeMaxDynamicSharedMemorySize, SM_POST);

  k_zero<<<(NN*160 + 4*NG_ + 255)/256, 256>>>();
  k_node_pre<<<148, 512, SM_PRE>>>(nf, oh, lpWs, lpbs, lpWv, scWs, scWv);
  k_mlp<<<296, 512, SM_MLP>>>(ele, fcW1, fcb1, fcW2, fcb2, fcW3, fcb3);
  k_edge<<<592, 256, SM_EDGE>>>(eidx, esh, efea, Wss0, Wvv0, Wssg, Wvvg, Wsv1, Wvs1);
  k_node_post<<<148, 512, SM_POST>>>(batch, ppWs, ppbs, ppWv);
  k_groups<<<1, 32>>>();
  k_out<<<(NN*160 + 255)/256, 256>>>(nf, batch, lnws, lnbs, lnwv, out);
}

// round 4
// speedup vs baseline: 1.4122x; 1.1308x over previous
#include <cuda_runtime.h>

#define NN 10000
#define EE 320000
#define NG_ 16

// ---------------- scratch (static device memory; no allocations) ----------------
__device__ float  g_s[NN*64];
__device__ float4 g_v4[NN*32];
__device__ float  g_scs[NN*64];
__device__ float  g_scv[NN*96];
__device__ float  g_accs[NN*64];
__device__ float  g_accv[NN*96];
__device__ float  g_ns[NN*64];
__device__ float  g_nv[NN*96];
__device__ float  g_wmlp[(long long)EE*96];
__device__ float  g_e1[(long long)EE*128];   // per-edge (a0,a1,ag,at) x 32 lanes
__device__ float  g_gstat[4*NG_];
__device__ float  g_gout[3*NG_];

__device__ __forceinline__ float sig_(float x){ return 1.f/(1.f+__expf(-x)); }

// ---- f32x2 packed math helpers (sm_103a FFMA2 via PTX) ----
__device__ __forceinline__ unsigned long long pk2(float x){
  unsigned long long r; asm("mov.b64 %0, {%1, %1};" : "=l"(r) : "f"(x)); return r; }
__device__ __forceinline__ unsigned long long pkab(float a, float b){
  unsigned long long r; asm("mov.b64 %0, {%1, %2};" : "=l"(r) : "f"(a), "f"(b)); return r; }
__device__ __forceinline__ void up2(unsigned long long v, float &a, float &b){
  asm("mov.b64 {%0, %1}, %2;" : "=f"(a), "=f"(b) : "l"(v)); }
__device__ __forceinline__ void fma2(unsigned long long &d, unsigned long long a, unsigned long long b){
  asm("fma.rn.f32x2 %0, %1, %2, %3;" : "=l"(d) : "l"(a), "l"(b), "l"(d)); }

// ---------------- zero accumulators ----------------
__global__ void k_zero(){
  int i = blockIdx.x*blockDim.x + threadIdx.x;
  if (i < NN*64) g_accs[i] = 0.f;
  int j = i - NN*64;
  if (j >= 0 && j < NN*96) g_accv[j] = 0.f;
  int k = i - NN*160;
  if (k >= 0 && k < 4*NG_) g_gstat[k] = 0.f;
}

// ---------------- node pre ----------------
__global__ void __launch_bounds__(512) k_node_pre(const float* __restrict__ nf,
                           const float* __restrict__ oh,
                           const float* __restrict__ lpWs, const float* __restrict__ lpbs,
                           const float* __restrict__ lpWv,
                           const float* __restrict__ scWs, const float* __restrict__ scWv){
  extern __shared__ float sm[];
  float2* WsS  = (float2*)sm;
  float*  WvS  = sm + 4096;
  float2* sWsS = (float2*)(sm + 5120);
  float*  sWvS = sm + 21504;
  float*  bsS  = sm + 25600;
  float*  stage= sm + 25664;

  for (int i=threadIdx.x;i<4096;i+=blockDim.x) sm[i]=lpWs[i];
  for (int i=threadIdx.x;i<1024;i+=blockDim.x) WvS[i]=lpWv[i];
  for (int i=threadIdx.x;i<16384;i+=blockDim.x) sm[5120+i]=scWs[i];
  for (int i=threadIdx.x;i<4096;i+=blockDim.x) sWvS[i]=scWv[i];
  for (int i=threadIdx.x;i<64;i+=blockDim.x) bsS[i]=lpbs[i];
  __syncthreads();

  int warp = threadIdx.x>>5, lane = threadIdx.x&31, wpb = blockDim.x>>5;
  float*  sS  = stage + warp*192;
  float4* vS  = (float4*)(sS + 64);

  for (int n = blockIdx.x*wpb + warp; n < NN; n += gridDim.x*wpb){
    const float* row = nf + n*160;
    sS[lane] = row[lane]; sS[32+lane] = row[32+lane];
    vS[lane] = make_float4(row[64+3*lane], row[65+3*lane], row[66+3*lane], 0.f);
    const float* o4 = oh + n*4;
    int sp = (o4[1]>0.5f)?1:((o4[2]>0.5f)?2:((o4[3]>0.5f)?3:0));
    __syncwarp();

    float a0=0.f,a1=0.f,c0=0.f,c1=0.f;
    #pragma unroll 4
    for (int u=0;u<64;u++){
      float x = sS[u];
      float2 w  = WsS[u*32+lane];
      float2 w2 = sWsS[(u*4+sp)*32+lane];
      a0+=x*w.x; a1+=x*w.y; c0+=x*w2.x; c1+=x*w2.y;
    }
    g_s[n*64+2*lane]   = a0*0.125f + bsS[2*lane];
    g_s[n*64+2*lane+1] = a1*0.125f + bsS[2*lane+1];
    g_scs[n*64+2*lane]   = c0*0.0625f;
    g_scs[n*64+2*lane+1] = c1*0.0625f;

    float vx=0.f,vy=0.f,vz=0.f,cx=0.f,cy=0.f,cz=0.f;
    #pragma unroll 4
    for (int u=0;u<32;u++){
      float4 x = vS[u];
      float w  = WvS[u*32+lane];
      float w2 = sWvS[(u*4+sp)*32+lane];
      vx+=x.x*w;  vy+=x.y*w;  vz+=x.z*w;
      cx+=x.x*w2; cy+=x.y*w2; cz+=x.z*w2;
    }
    g_v4[n*32+lane] = make_float4(vx*0.17677670f, vy*0.17677670f, vz*0.17677670f, 0.f);
    g_scv[n*96+3*lane]   = cx*0.08838835f;
    g_scv[n*96+3*lane+1] = cy*0.08838835f;
    g_scv[n*96+3*lane+2] = cz*0.08838835f;
    __syncwarp();
  }
}

// ---------------- per-edge MLP (128->64->64->96), 8 edges/warp, f32x2 ----------------
__global__ void __launch_bounds__(512) k_mlp(const float* __restrict__ ele,
   const float* __restrict__ W1, const float* __restrict__ b1,
   const float* __restrict__ W2, const float* __restrict__ b2,
   const float* __restrict__ W3, const float* __restrict__ b3){
  extern __shared__ float sm[];
  float* b1S = sm+18432; float* b2S = sm+18496; float* b3S = sm+18560;
  float* stage = sm+18656;

  for (int i=threadIdx.x;i<8192;i+=blockDim.x) sm[i]=W1[i];
  for (int i=threadIdx.x;i<4096;i+=blockDim.x) sm[8192+i]=W2[i];
  for (int i=threadIdx.x;i<2048;i+=blockDim.x){
    int j=i>>5, l=i&31;
    ((float2*)(sm+12288))[i] = make_float2(W3[j*96+l], W3[j*96+32+l]);
    sm[16384+i] = W3[j*96+64+l];
  }
  for (int i=threadIdx.x;i<64;i+=blockDim.x){ b1S[i]=b1[i]; b2S[i]=b2[i]; }
  for (int i=threadIdx.x;i<96;i+=blockDim.x) b3S[i]=b3[i];
  __syncthreads();

  int warp=threadIdx.x>>5, lane=threadIdx.x&31, wpb=blockDim.x>>5;
  float* st = stage + warp*2048;

  unsigned long long bias1 = pkab(b1S[2*lane], b1S[2*lane+1]);
  unsigned long long bias2 = pkab(b2S[2*lane], b2S[2*lane+1]);
  unsigned long long bias3 = pkab(b3S[lane],   b3S[32+lane]);
  float bias3s = b3S[64+lane];

  const int octs = EE/8;
  for (int p = blockIdx.x*wpb+warp; p<octs; p+=gridDim.x*wpb){
    long long e0 = 8LL*p;
    #pragma unroll
    for (int k=0;k<8;k++){
      const float* r = ele + (e0+k)*128;
      float* eE = st + k*256;
      #pragma unroll
      for (int c=0;c<4;c++) eE[c*32+lane]=r[c*32+lane];
    }
    __syncwarp();

    unsigned long long acc[8];
    #pragma unroll
    for (int k=0;k<8;k++) acc[k]=bias1;
    #pragma unroll 2
    for (int j=0;j<128;j+=4){
      unsigned long long w0=*(unsigned long long*)(sm+ (j  )*64 + 2*lane);
      unsigned long long w1=*(unsigned long long*)(sm+ (j+1)*64 + 2*lane);
      unsigned long long w2=*(unsigned long long*)(sm+ (j+2)*64 + 2*lane);
      unsigned long long w3=*(unsigned long long*)(sm+ (j+3)*64 + 2*lane);
      #pragma unroll
      for (int k=0;k<8;k++){
        float4 x = *(float4*)(st + k*256 + j);
        fma2(acc[k], pk2(x.x), w0);
        fma2(acc[k], pk2(x.y), w1);
        fma2(acc[k], pk2(x.z), w2);
        fma2(acc[k], pk2(x.w), w3);
      }
    }
    #pragma unroll
    for (int k=0;k<8;k++){
      float a0,a1; up2(acc[k],a0,a1);
      float* hE = st + k*256 + 128;
      hE[2*lane]=a0*sig_(a0); hE[2*lane+1]=a1*sig_(a1);
    }
    __syncwarp();

    #pragma unroll
    for (int k=0;k<8;k++) acc[k]=bias2;
    #pragma unroll 2
    for (int j=0;j<64;j+=4){
      unsigned long long w0=*(unsigned long long*)(sm+8192+(j  )*64 + 2*lane);
      unsigned long long w1=*(unsigned long long*)(sm+8192+(j+1)*64 + 2*lane);
      unsigned long long w2=*(unsigned long long*)(sm+8192+(j+2)*64 + 2*lane);
      unsigned long long w3=*(unsigned long long*)(sm+8192+(j+3)*64 + 2*lane);
      #pragma unroll
      for (int k=0;k<8;k++){
        float4 x = *(float4*)(st + k*256 + 128 + j);
        fma2(acc[k], pk2(x.x), w0);
        fma2(acc[k], pk2(x.y), w1);
        fma2(acc[k], pk2(x.z), w2);
        fma2(acc[k], pk2(x.w), w3);
      }
    }
    #pragma unroll
    for (int k=0;k<8;k++){
      float a0,a1; up2(acc[k],a0,a1);
      float* gE = st + k*256 + 192;
      gE[2*lane]=a0*sig_(a0); gE[2*lane+1]=a1*sig_(a1);
    }
    __syncwarp();

    unsigned long long c01[8]; float c2[8];
    #pragma unroll
    for (int k=0;k<8;k++){ c01[k]=bias3; c2[k]=bias3s; }
    #pragma unroll 2
    for (int j=0;j<64;j+=4){
      unsigned long long p0=*(unsigned long long*)(sm+12288+(j  )*64 + 2*lane);
      unsigned long long p1=*(unsigned long long*)(sm+12288+(j+1)*64 + 2*lane);
      unsigned long long p2=*(unsigned long long*)(sm+12288+(j+2)*64 + 2*lane);
      unsigned long long p3=*(unsigned long long*)(sm+12288+(j+3)*64 + 2*lane);
      float s0=sm[16384+(j  )*32+lane];
      float s1=sm[16384+(j+1)*32+lane];
      float s2=sm[16384+(j+2)*32+lane];
      float s3=sm[16384+(j+3)*32+lane];
      #pragma unroll
      for (int k=0;k<8;k++){
        float4 x = *(float4*)(st + k*256 + 192 + j);
        fma2(c01[k], pk2(x.x), p0); c2[k]+=x.x*s0;
        fma2(c01[k], pk2(x.y), p1); c2[k]+=x.y*s1;
        fma2(c01[k], pk2(x.z), p2); c2[k]+=x.z*s2;
        fma2(c01[k], pk2(x.w), p3); c2[k]+=x.w*s3;
      }
    }
    #pragma unroll
    for (int k=0;k<8;k++){
      float a,b; up2(c01[k],a,b);
      float* wo = g_wmlp + (e0+k)*96;
      wo[lane]=a; wo[32+lane]=b; wo[64+lane]=c2[k];
    }
    __syncwarp();
  }
}

// ---------------- E1: s-channel GEMV (192 -> 128), 8 edges/warp, 16 warps ----------------
__global__ void __launch_bounds__(512) k_e1(const int* __restrict__ eidx,
   const float* __restrict__ efea,
   const float* __restrict__ Wss0, const float* __restrict__ Wssg,
   const float* __restrict__ Wsv1){
  extern __shared__ float sm[];
  float4* F1 = (float4*)sm;            // 192x32 f4 = 98304 B
  float* stage = sm + 24576;           // 16 warps x 1536 f

  for (int i=threadIdx.x;i<6144;i+=blockDim.x){
    int u=i>>5, l=i&31;
    F1[i]=make_float4(Wss0[u*64+2*l], Wss0[u*64+2*l+1], Wssg[u*32+l], Wsv1[u*32+l]);
  }
  __syncthreads();

  int warp=threadIdx.x>>5, lane=threadIdx.x&31, wpb=blockDim.x>>5;
  float* sW = stage + warp*1536;
  const int octs = EE/8;

  for (int p = blockIdx.x*wpb+warp; p<octs; p+=gridDim.x*wpb){
    int e0 = 8*p;
    #pragma unroll
    for (int k=0;k<8;k++){
      int e = e0+k;
      int ni=eidx[e], nj=eidx[EE+e];
      const float* r = efea + (long long)e*160;
      float* s1k = sW + k*192;
      s1k[lane]     = g_s[ni*64+lane];
      s1k[32+lane]  = g_s[ni*64+32+lane];
      s1k[64+lane]  = g_s[nj*64+lane];
      s1k[96+lane]  = g_s[nj*64+32+lane];
      s1k[128+lane] = r[lane];
      s1k[160+lane] = r[32+lane];
    }
    __syncwarp();

    unsigned long long a01[8], agt[8];
    #pragma unroll
    for (int k=0;k<8;k++){ a01[k]=0ull; agt[k]=0ull; }
    #pragma unroll 1
    for (int u=0;u<192;u+=4){
      ulonglong2 w0=*(ulonglong2*)&F1[(u  )*32+lane];
      ulonglong2 w1=*(ulonglong2*)&F1[(u+1)*32+lane];
      ulonglong2 w2=*(ulonglong2*)&F1[(u+2)*32+lane];
      ulonglong2 w3=*(ulonglong2*)&F1[(u+3)*32+lane];
      #pragma unroll
      for (int k=0;k<8;k++){
        float4 x = *(float4*)(sW + k*192 + u);
        unsigned long long xx;
        xx=pk2(x.x); fma2(a01[k],xx,w0.x); fma2(agt[k],xx,w0.y);
        xx=pk2(x.y); fma2(a01[k],xx,w1.x); fma2(agt[k],xx,w1.y);
        xx=pk2(x.z); fma2(a01[k],xx,w2.x); fma2(agt[k],xx,w2.y);
        xx=pk2(x.w); fma2(a01[k],xx,w3.x); fma2(agt[k],xx,w3.y);
      }
    }
    #pragma unroll
    for (int k=0;k<8;k++){
      float a0,a1,ag,at;
      up2(a01[k],a0,a1); up2(agt[k],ag,at);
      *(float4*)(g_e1 + (long long)(e0+k)*128 + lane*4) = make_float4(a0,a1,ag,at);
    }
    __syncwarp();
  }
}

// ---------------- E2: v-channel GEMV + epilogue + scatter, 6 edges/warp, 16 warps ----------------
__global__ void __launch_bounds__(512) k_e2(const int* __restrict__ eidx,
   const float* __restrict__ esh, const float* __restrict__ efea,
   const float* __restrict__ Wvv0, const float* __restrict__ Wvvg,
   const float* __restrict__ Wvs1){
  extern __shared__ float sm[];
  float4* F2 = (float4*)sm;            // 96x32 f4 = 49152 B
  float* stage = sm + 12288;           // 16 warps x 2304 f (6 edges x 96 f4)

  for (int i=threadIdx.x;i<3072;i+=blockDim.x){
    int u=i>>5, l=i&31;
    F2[i]=make_float4(Wvv0[u*64+2*l], Wvv0[u*64+2*l+1], Wvvg[u*32+l], Wvs1[u*32+l]);
  }
  __syncthreads();

  int warp=threadIdx.x>>5, lane=threadIdx.x&31, wpb=blockDim.x>>5;
  float4* vW = (float4*)stage + warp*576;
  const float inv3 = 0.57735027f, invfan = 0.058925565f;
  const int grps = (EE+5)/6;

  for (int p = blockIdx.x*wpb+warp; p<grps; p+=gridDim.x*wpb){
    int ebase = 6*p;
    int ni[6]; float4 shv[6];
    #pragma unroll
    for (int k=0;k<6;k++){
      int e = ebase+k;
      float4* vk = vW + k*96;
      if (e < EE){
        ni[k]=eidx[e]; int nj=eidx[EE+e];
        float4 sh = *(const float4*)(esh + (long long)e*4);
        shv[k]=sh;
        const float* r = efea + (long long)e*160;
        float4 v = g_v4[ni[k]*32+lane];
        v.w=(v.x*sh.y+v.y*sh.z+v.z*sh.w)*inv3; vk[lane]=v;
        v = g_v4[nj*32+lane];
        v.w=(v.x*sh.y+v.y*sh.z+v.z*sh.w)*inv3; vk[32+lane]=v;
        float ex=r[64+3*lane], ey=r[65+3*lane], ez=r[66+3*lane];
        vk[64+lane]=make_float4(ex,ey,ez,(ex*sh.y+ey*sh.z+ez*sh.w)*inv3);
      } else {
        ni[k]=-1;
        float4 z=make_float4(0.f,0.f,0.f,0.f);
        vk[lane]=z; vk[32+lane]=z; vk[64+lane]=z;
        shv[k]=z;
      }
    }
    __syncwarp();

    unsigned long long b01[6], r01[6], gz2[6];
    #pragma unroll
    for (int k=0;k<6;k++){ b01[k]=0ull; r01[k]=0ull; gz2[k]=0ull; }
    #pragma unroll 2
    for (int u=0;u<96;u++){
      ulonglong2 w = *(ulonglong2*)&F2[u*32+lane];
      float wz,ww; up2(w.y, wz, ww);
      unsigned long long www = pk2(ww);
      #pragma unroll
      for (int k=0;k<6;k++){
        float4 v = vW[k*96+u];
        fma2(b01[k], pk2(v.w), w.x);
        fma2(r01[k], pkab(v.x,v.y), www);
        fma2(gz2[k], pkab(v.w,v.z), w.y);   // (dd*wz, vz*ww) = (bg, r2)
      }
    }

    #pragma unroll
    for (int k=0;k<6;k++){
      if (ni[k] < 0) continue;
      long long e = ebase+k;
      float b0,b1,r0,r1,bg,r2;
      up2(b01[k],b0,b1); up2(r01[k],r0,r1); up2(gz2[k],bg,r2);
      float4 f1v = *(const float4*)(g_e1 + e*128 + lane*4);  // a0,a1,ag,at
      float4 sh = shv[k];
      float zs0=(sh.x*f1v.x+b0)*invfan, zs1=(sh.x*f1v.y+b1)*invfan;
      float zg =(sh.x*f1v.z+bg)*invfan;
      float at = f1v.w;
      const float* wm = g_wmlp + e*96;
      float2 wm01 = *(const float2*)(wm+2*lane);
      float wmv = wm[64+lane];
      zs0 = zs0*sig_(zs0)*wm01.x;
      zs1 = zs1*sig_(zs1)*wm01.y;
      float gv = sig_(zg)*wmv*invfan;
      int n = ni[k];
      atomicAdd(&g_accs[n*64+2*lane],   zs0);
      atomicAdd(&g_accs[n*64+2*lane+1], zs1);
      atomicAdd(&g_accv[n*96+3*lane],   (at*sh.y + r0*sh.x)*gv);
      atomicAdd(&g_accv[n*96+3*lane+1], (at*sh.z + r1*sh.x)*gv);
      atomicAdd(&g_accv[n*96+3*lane+2], (at*sh.w + r2*sh.x)*gv);
    }
    __syncwarp();
  }
}

// ---------------- node post ----------------
__global__ void __launch_bounds__(512) k_node_post(const int* __restrict__ batch,
   const float* __restrict__ ppWs, const float* __restrict__ ppbs,
   const float* __restrict__ ppWv){
  extern __shared__ float sm[];
  float2* WsS = (float2*)sm;
  float* WvS = sm+4096;
  float* bsS = sm+5120;
  float* stage = sm+5184;
  for (int i=threadIdx.x;i<4096;i+=blockDim.x) sm[i]=ppWs[i];
  for (int i=threadIdx.x;i<1024;i+=blockDim.x) WvS[i]=ppWv[i];
  for (int i=threadIdx.x;i<64;i+=blockDim.x) bsS[i]=ppbs[i];
  __syncthreads();
  int warp=threadIdx.x>>5, lane=threadIdx.x&31, wpb=blockDim.x>>5;
  float*  sS  = stage + warp*192;
  float4* vS  = (float4*)(sS+64);
  for (int n=blockIdx.x*wpb+warp; n<NN; n+=gridDim.x*wpb){
    sS[lane]=g_accs[n*64+lane]; sS[32+lane]=g_accs[n*64+32+lane];
    vS[lane]=make_float4(g_accv[n*96+3*lane],g_accv[n*96+3*lane+1],g_accv[n*96+3*lane+2],0.f);
    __syncwarp();
    float a0=0.f,a1=0.f;
    #pragma unroll 4
    for (int u=0;u<64;u++){
      float x=sS[u]; float2 w=WsS[u*32+lane];
      a0+=x*w.x; a1+=x*w.y;
    }
    float ns0 = a0*0.125f + bsS[2*lane]   + g_scs[n*64+2*lane];
    float ns1 = a1*0.125f + bsS[2*lane+1] + g_scs[n*64+2*lane+1];
    g_ns[n*64+2*lane]=ns0; g_ns[n*64+2*lane+1]=ns1;
    float vx=0.f,vy=0.f,vz=0.f;
    #pragma unroll 4
    for (int u=0;u<32;u++){
      float4 x=vS[u]; float w=WvS[u*32+lane];
      vx+=x.x*w; vy+=x.y*w; vz+=x.z*w;
    }
    float nv0 = vx*0.17677670f + g_scv[n*96+3*lane];
    float nv1 = vy*0.17677670f + g_scv[n*96+3*lane+1];
    float nv2 = vz*0.17677670f + g_scv[n*96+3*lane+2];
    g_nv[n*96+3*lane]=nv0; g_nv[n*96+3*lane+1]=nv1; g_nv[n*96+3*lane+2]=nv2;
    float m = ns0+ns1;
    float q = ns0*ns0+ns1*ns1;
    float pw = nv0*nv0+nv1*nv1+nv2*nv2;
    #pragma unroll
    for (int off=16;off>0;off>>=1){
      m += __shfl_down_sync(0xffffffffu, m, off);
      q += __shfl_down_sync(0xffffffffu, q, off);
      pw += __shfl_down_sync(0xffffffffu, pw, off);
    }
    if (lane==0){
      int g = batch[n];
      atomicAdd(&g_gstat[g],        m*(1.f/64.f));
      atomicAdd(&g_gstat[NG_+g],    q*(1.f/64.f));
      atomicAdd(&g_gstat[2*NG_+g],  pw*(1.f/96.f));
      atomicAdd(&g_gstat[3*NG_+g],  1.f);
    }
    __syncwarp();
  }
}

// ---------------- group finalize ----------------
__global__ void k_groups(){
  int t = threadIdx.x;
  if (t < NG_){
    float c  = fmaxf(g_gstat[3*NG_+t], 1.f);
    float mu = g_gstat[t]/c;
    float vs = g_gstat[NG_+t]/c - mu*mu;
    float vv = g_gstat[2*NG_+t]/c;
    g_gout[t]       = mu;
    g_gout[NG_+t]   = rsqrtf(vs+1e-5f);
    g_gout[2*NG_+t] = rsqrtf(vv+1e-5f);
  }
}

// ---------------- apply norm + residual ----------------
__global__ void k_out(const float* __restrict__ nf, const int* __restrict__ batch,
   const float* __restrict__ lnws, const float* __restrict__ lnbs,
   const float* __restrict__ lnwv, float* __restrict__ out){
  int i = blockIdx.x*blockDim.x+threadIdx.x;
  if (i >= NN*160) return;
  int n = i/160, c = i - n*160;
  int g = batch[n];
  float base = nf[i];
  float o;
  if (c < 64){
    float x = (g_ns[n*64+c] - g_gout[g]) * g_gout[NG_+g];
    o = base + x*lnws[c] + lnbs[c];
  } else {
    int cc = c-64;
    o = base + g_nv[n*96+cc]*g_gout[2*NG_+g]*lnwv[cc/3];
  }
  out[i]=o;
}

// ---------------- launcher ----------------
extern "C" void kernel_launch(void* const* d_in, const int* in_sizes, int n_in,
                              void* d_out, int out_size){
  const float* nf   =(const float*)d_in[0];
  const float* oh   =(const float*)d_in[1];
  const float* esh  =(const float*)d_in[2];
  const float* efea =(const float*)d_in[3];
  const float* ele  =(const float*)d_in[4];
  const int*   eidx =(const int*)d_in[5];
  const int*   batch=(const int*)d_in[6];
  const float* lpWs =(const float*)d_in[7];
  const float* lpbs =(const float*)d_in[8];
  const float* lpWv =(const float*)d_in[9];
  const float* ppWs =(const float*)d_in[10];
  const float* ppbs =(const float*)d_in[11];
  const float* ppWv =(const float*)d_in[12];
  const float* scWs =(const float*)d_in[13];
  const float* scWv =(const float*)d_in[14];
  const float* Wss0 =(const float*)d_in[15];
  const float* Wvv0 =(const float*)d_in[16];
  const float* Wssg =(const float*)d_in[17];
  const float* Wvvg =(const float*)d_in[18];
  const float* Wsv1 =(const float*)d_in[19];
  const float* Wvs1 =(const float*)d_in[20];
  const float* fcW1 =(const float*)d_in[21];
  const float* fcb1 =(const float*)d_in[22];
  const float* fcW2 =(const float*)d_in[23];
  const float* fcb2 =(const float*)d_in[24];
  const float* fcW3 =(const float*)d_in[25];
  const float* fcb3 =(const float*)d_in[26];
  const float* lnws =(const float*)d_in[27];
  const float* lnbs =(const float*)d_in[28];
  const float* lnwv =(const float*)d_in[29];
  float* out = (float*)d_out;

  const int SM_PRE  = (25664 + 16*192)*4;    // 114944
  const int SM_MLP  = (18656 + 16*2048)*4;   // 205696
  const int SM_E1   = (24576 + 16*1536)*4;   // 196608
  const int SM_E2   = (12288 + 16*2304)*4;   // 196608
  const int SM_POST = (5184  + 16*192)*4;    // 33024
  cudaFuncSetAttribute(k_node_pre,  cudaFuncAttributeMaxDynamicSharedMemorySize, SM_PRE);
  cudaFuncSetAttribute(k_mlp,       cudaFuncAttributeMaxDynamicSharedMemorySize, SM_MLP);
  cudaFuncSetAttribute(k_e1,        cudaFuncAttributeMaxDynamicSharedMemorySize, SM_E1);
  cudaFuncSetAttribute(k_e2,        cudaFuncAttributeMaxDynamicSharedMemorySize, SM_E2);
  cudaFuncSetAttribute(k_node_post, cudaFuncAttributeMaxDynamicSharedMemorySize, SM_POST);

  k_zero<<<(NN*160 + 4*NG_ + 255)/256, 256>>>();
  k_node_pre<<<148, 512, SM_PRE>>>(nf, oh, lpWs, lpbs, lpWv, scWs, scWv);
  k_mlp<<<296, 512, SM_MLP>>>(ele, fcW1, fcb1, fcW2, fcb2, fcW3, fcb3);
  k_e1<<<592, 512, SM_E1>>>(eidx, efea, Wss0, Wssg, Wsv1);
  k_e2<<<592, 512, SM_E2>>>(eidx, esh, efea, Wvv0, Wvvg, Wvs1);
  k_node_post<<<148, 512, SM_POST>>>(batch, ppWs, ppbs, ppWv);
  k_groups<<<1, 32>>>();
  k_out<<<(NN*160 + 255)/256, 256>>>(nf, batch, lnws, lnbs, lnwv, out);
}

// round 5
// speedup vs baseline: 1.8844x; 1.3344x over previous
#include <cuda_runtime.h>

#define NN 10000
#define EE 320000
#define NG_ 16

// ---------------- scratch (static device memory; no allocations) ----------------
__device__ float  g_s[NN*64];
__device__ float4 g_v4[NN*32];
__device__ float  g_scs[NN*64];
__device__ float  g_scv[NN*96];
__device__ float  g_accs[NN*64];
__device__ float  g_accv[NN*96];
__device__ float  g_ns[NN*64];
__device__ float  g_nv[NN*96];
__device__ float  g_wmlp[(long long)EE*96];
__device__ float  g_e1[(long long)EE*128];   // per-edge (a0,a1,ag,at) x 32 lanes
__device__ float  g_P[NN*128];               // s@F1[0:64]   (i-role), lane*4 layout
__device__ float  g_Q[NN*128];               // s@F1[64:128] (j-role)
__device__ float  g_T[NN*384];               // v x F2[0:32]  (i-role), lane*12 layout
__device__ float  g_U[NN*384];               // v x F2[32:64] (j-role)
__device__ float  g_gstat[4*NG_];
__device__ float  g_gout[3*NG_];

__device__ __forceinline__ float sig_(float x){ return 1.f/(1.f+__expf(-x)); }

// ---- f32x2 packed math helpers (sm_103a FFMA2 via PTX) ----
__device__ __forceinline__ unsigned long long pk2(float x){
  unsigned long long r; asm("mov.b64 %0, {%1, %1};" : "=l"(r) : "f"(x)); return r; }
__device__ __forceinline__ unsigned long long pkab(float a, float b){
  unsigned long long r; asm("mov.b64 %0, {%1, %2};" : "=l"(r) : "f"(a), "f"(b)); return r; }
__device__ __forceinline__ void up2(unsigned long long v, float &a, float &b){
  asm("mov.b64 {%0, %1}, %2;" : "=f"(a), "=f"(b) : "l"(v)); }
__device__ __forceinline__ void fma2(unsigned long long &d, unsigned long long a, unsigned long long b){
  asm("fma.rn.f32x2 %0, %1, %2, %3;" : "=l"(d) : "l"(a), "l"(b), "l"(d)); }

// ---------------- zero accumulators ----------------
__global__ void k_zero(){
  int i = blockIdx.x*blockDim.x + threadIdx.x;
  if (i < NN*64) g_accs[i] = 0.f;
  int j = i - NN*64;
  if (j >= 0 && j < NN*96) g_accv[j] = 0.f;
  int k = i - NN*160;
  if (k >= 0 && k < 4*NG_) g_gstat[k] = 0.f;
}

// ---------------- node pre ----------------
__global__ void __launch_bounds__(512) k_node_pre(const float* __restrict__ nf,
                           const float* __restrict__ oh,
                           const float* __restrict__ lpWs, const float* __restrict__ lpbs,
                           const float* __restrict__ lpWv,
                           const float* __restrict__ scWs, const float* __restrict__ scWv){
  extern __shared__ float sm[];
  float2* WsS  = (float2*)sm;
  float*  WvS  = sm + 4096;
  float2* sWsS = (float2*)(sm + 5120);
  float*  sWvS = sm + 21504;
  float*  bsS  = sm + 25600;
  float*  stage= sm + 25664;

  for (int i=threadIdx.x;i<4096;i+=blockDim.x) sm[i]=lpWs[i];
  for (int i=threadIdx.x;i<1024;i+=blockDim.x) WvS[i]=lpWv[i];
  for (int i=threadIdx.x;i<16384;i+=blockDim.x) sm[5120+i]=scWs[i];
  for (int i=threadIdx.x;i<4096;i+=blockDim.x) sWvS[i]=scWv[i];
  for (int i=threadIdx.x;i<64;i+=blockDim.x) bsS[i]=lpbs[i];
  __syncthreads();

  int warp = threadIdx.x>>5, lane = threadIdx.x&31, wpb = blockDim.x>>5;
  float*  sS  = stage + warp*192;
  float4* vS  = (float4*)(sS + 64);

  for (int n = blockIdx.x*wpb + warp; n < NN; n += gridDim.x*wpb){
    const float* row = nf + n*160;
    sS[lane] = row[lane]; sS[32+lane] = row[32+lane];
    vS[lane] = make_float4(row[64+3*lane], row[65+3*lane], row[66+3*lane], 0.f);
    const float* o4 = oh + n*4;
    int sp = (o4[1]>0.5f)?1:((o4[2]>0.5f)?2:((o4[3]>0.5f)?3:0));
    __syncwarp();

    float a0=0.f,a1=0.f,c0=0.f,c1=0.f;
    #pragma unroll 4
    for (int u=0;u<64;u++){
      float x = sS[u];
      float2 w  = WsS[u*32+lane];
      float2 w2 = sWsS[(u*4+sp)*32+lane];
      a0+=x*w.x; a1+=x*w.y; c0+=x*w2.x; c1+=x*w2.y;
    }
    g_s[n*64+2*lane]   = a0*0.125f + bsS[2*lane];
    g_s[n*64+2*lane+1] = a1*0.125f + bsS[2*lane+1];
    g_scs[n*64+2*lane]   = c0*0.0625f;
    g_scs[n*64+2*lane+1] = c1*0.0625f;

    float vx=0.f,vy=0.f,vz=0.f,cx=0.f,cy=0.f,cz=0.f;
    #pragma unroll 4
    for (int u=0;u<32;u++){
      float4 x = vS[u];
      float w  = WvS[u*32+lane];
      float w2 = sWvS[(u*4+sp)*32+lane];
      vx+=x.x*w;  vy+=x.y*w;  vz+=x.z*w;
      cx+=x.x*w2; cy+=x.y*w2; cz+=x.z*w2;
    }
    g_v4[n*32+lane] = make_float4(vx*0.17677670f, vy*0.17677670f, vz*0.17677670f, 0.f);
    g_scv[n*96+3*lane]   = cx*0.08838835f;
    g_scv[n*96+3*lane+1] = cy*0.08838835f;
    g_scv[n*96+3*lane+2] = cz*0.08838835f;
    __syncwarp();
  }
}

// ---------------- per-node P/Q: s @ F1 rows[0:64] and [64:128], 8 nodes/warp ----------------
__global__ void __launch_bounds__(512) k_ps(const float* __restrict__ Wss0,
   const float* __restrict__ Wssg, const float* __restrict__ Wsv1){
  extern __shared__ float sm[];
  float4* FA = (float4*)sm;            // rows 0..63:  64x32 f4
  float4* FB = (float4*)(sm+8192);     // rows 64..127
  float* stage = sm + 16384;           // per warp 1024 f (8 nodes x 128 dup)

  for (int i=threadIdx.x;i<2048;i+=blockDim.x){
    int u=i>>5, l=i&31;
    FA[i]=make_float4(Wss0[u*64+2*l], Wss0[u*64+2*l+1], Wssg[u*32+l], Wsv1[u*32+l]);
    int u2=u+64;
    FB[i]=make_float4(Wss0[u2*64+2*l], Wss0[u2*64+2*l+1], Wssg[u2*32+l], Wsv1[u2*32+l]);
  }
  __syncthreads();

  int warp=threadIdx.x>>5, lane=threadIdx.x&31, wpb=blockDim.x>>5;
  float* sd = stage + warp*1024;
  const int batches = NN/8;

  for (int p = blockIdx.x*wpb+warp; p<batches; p+=gridDim.x*wpb){
    int n0 = p*8;
    #pragma unroll
    for (int k=0;k<8;k++){
      int n = n0+k;
      float x0 = g_s[n*64+lane];
      float x1 = g_s[n*64+32+lane];
      *(unsigned long long*)(sd + k*128 + 2*lane)      = pkab(x0,x0);
      *(unsigned long long*)(sd + k*128 + 64 + 2*lane) = pkab(x1,x1);
    }
    __syncwarp();

    unsigned long long pa[8], pg[8], qa[8], qg[8];
    #pragma unroll
    for (int k=0;k<8;k++){ pa[k]=0ull; pg[k]=0ull; qa[k]=0ull; qg[k]=0ull; }
    #pragma unroll 2
    for (int u=0;u<64;u+=2){
      ulonglong2 wa0 = *(ulonglong2*)&FA[(u  )*32+lane];
      ulonglong2 wa1 = *(ulonglong2*)&FA[(u+1)*32+lane];
      ulonglong2 wb0 = *(ulonglong2*)&FB[(u  )*32+lane];
      ulonglong2 wb1 = *(ulonglong2*)&FB[(u+1)*32+lane];
      #pragma unroll
      for (int k=0;k<8;k++){
        ulonglong2 xp = *(ulonglong2*)(sd + k*128 + 2*u);
        fma2(pa[k], xp.x, wa0.x); fma2(pg[k], xp.x, wa0.y);
        fma2(qa[k], xp.x, wb0.x); fma2(qg[k], xp.x, wb0.y);
        fma2(pa[k], xp.y, wa1.x); fma2(pg[k], xp.y, wa1.y);
        fma2(qa[k], xp.y, wb1.x); fma2(qg[k], xp.y, wb1.y);
      }
    }
    #pragma unroll
    for (int k=0;k<8;k++){
      int n = n0+k;
      float a0,a1,ag,at;
      up2(pa[k],a0,a1); up2(pg[k],ag,at);
      *(float4*)(g_P + n*128 + lane*4) = make_float4(a0,a1,ag,at);
      up2(qa[k],a0,a1); up2(qg[k],ag,at);
      *(float4*)(g_Q + n*128 + lane*4) = make_float4(a0,a1,ag,at);
    }
    __syncwarp();
  }
}

// ---------------- per-node T/U: v x F2 rows[0:32] and [32:64], 4 nodes/warp ----------------
__global__ void __launch_bounds__(512) k_tv(const float* __restrict__ Wvv0,
   const float* __restrict__ Wvvg, const float* __restrict__ Wvs1){
  extern __shared__ float sm[];
  float4* GA = (float4*)sm;            // rows 0..31: 32x32 f4
  float4* GB = (float4*)(sm+4096);     // rows 32..63
  float4* stage = (float4*)(sm+8192);  // per warp 128 f4 (4 nodes x 32)

  for (int i=threadIdx.x;i<1024;i+=blockDim.x){
    int u=i>>5, l=i&31;
    GA[i]=make_float4(Wvv0[u*64+2*l], Wvv0[u*64+2*l+1], Wvvg[u*32+l], Wvs1[u*32+l]);
    int u2=u+32;
    GB[i]=make_float4(Wvv0[u2*64+2*l], Wvv0[u2*64+2*l+1], Wvvg[u2*32+l], Wvs1[u2*32+l]);
  }
  __syncthreads();

  int warp=threadIdx.x>>5, lane=threadIdx.x&31, wpb=blockDim.x>>5;
  float4* vst = stage + warp*128;
  const int batches = NN/4;

  for (int p = blockIdx.x*wpb+warp; p<batches; p+=gridDim.x*wpb){
    int n0 = p*4;
    #pragma unroll
    for (int k=0;k<4;k++) vst[k*32+lane] = g_v4[(n0+k)*32+lane];
    __syncwarp();

    // per node: T01{x,y,z} = ((b0,b1) per comp), Tgr{x,y,z} = ((bg,r) per comp); same for U
    unsigned long long t01[4][3], tgr[4][3], u01[4][3], ugr[4][3];
    #pragma unroll
    for (int k=0;k<4;k++)
      #pragma unroll
      for (int c=0;c<3;c++){ t01[k][c]=0ull; tgr[k][c]=0ull; u01[k][c]=0ull; ugr[k][c]=0ull; }

    #pragma unroll 2
    for (int u=0;u<32;u++){
      ulonglong2 ga = *(ulonglong2*)&GA[u*32+lane];
      ulonglong2 gb = *(ulonglong2*)&GB[u*32+lane];
      #pragma unroll
      for (int k=0;k<4;k++){
        float4 v = vst[k*32+u];
        unsigned long long vx=pk2(v.x), vy=pk2(v.y), vz=pk2(v.z);
        fma2(t01[k][0], vx, ga.x); fma2(t01[k][1], vy, ga.x); fma2(t01[k][2], vz, ga.x);
        fma2(tgr[k][0], vx, ga.y); fma2(tgr[k][1], vy, ga.y); fma2(tgr[k][2], vz, ga.y);
        fma2(u01[k][0], vx, gb.x); fma2(u01[k][1], vy, gb.x); fma2(u01[k][2], vz, gb.x);
        fma2(ugr[k][0], vx, gb.y); fma2(ugr[k][1], vy, gb.y); fma2(ugr[k][2], vz, gb.y);
      }
    }
    #pragma unroll
    for (int k=0;k<4;k++){
      int n = n0+k;
      float b0x,b1x,b0y,b1y,b0z,b1z,bgx,rx,bgy,ry,bgz,rz;
      up2(t01[k][0],b0x,b1x); up2(t01[k][1],b0y,b1y); up2(t01[k][2],b0z,b1z);
      up2(tgr[k][0],bgx,rx);  up2(tgr[k][1],bgy,ry);  up2(tgr[k][2],bgz,rz);
      float* o = g_T + n*384 + lane*12;
      *(float4*)(o  ) = make_float4(b0x,b0y,b0z,b1x);
      *(float4*)(o+4) = make_float4(b1y,b1z,bgx,bgy);
      *(float4*)(o+8) = make_float4(bgz,rx,ry,rz);
      up2(u01[k][0],b0x,b1x); up2(u01[k][1],b0y,b1y); up2(u01[k][2],b0z,b1z);
      up2(ugr[k][0],bgx,rx);  up2(ugr[k][1],bgy,ry);  up2(ugr[k][2],bgz,rz);
      o = g_U + n*384 + lane*12;
      *(float4*)(o  ) = make_float4(b0x,b0y,b0z,b1x);
      *(float4*)(o+4) = make_float4(b1y,b1z,bgx,bgy);
      *(float4*)(o+8) = make_float4(bgz,rx,ry,rz);
    }
    __syncwarp();
  }
}

// ---------------- per-edge MLP (128->64->64->96), 8 edges/warp, f32x2 ----------------
__global__ void __launch_bounds__(512) k_mlp(const float* __restrict__ ele,
   const float* __restrict__ W1, const float* __restrict__ b1,
   const float* __restrict__ W2, const float* __restrict__ b2,
   const float* __restrict__ W3, const float* __restrict__ b3){
  extern __shared__ float sm[];
  float* b1S = sm+18432; float* b2S = sm+18496; float* b3S = sm+18560;
  float* stage = sm+18656;

  for (int i=threadIdx.x;i<8192;i+=blockDim.x) sm[i]=W1[i];
  for (int i=threadIdx.x;i<4096;i+=blockDim.x) sm[8192+i]=W2[i];
  for (int i=threadIdx.x;i<2048;i+=blockDim.x){
    int j=i>>5, l=i&31;
    ((float2*)(sm+12288))[i] = make_float2(W3[j*96+l], W3[j*96+32+l]);
    sm[16384+i] = W3[j*96+64+l];
  }
  for (int i=threadIdx.x;i<64;i+=blockDim.x){ b1S[i]=b1[i]; b2S[i]=b2[i]; }
  for (int i=threadIdx.x;i<96;i+=blockDim.x) b3S[i]=b3[i];
  __syncthreads();

  int warp=threadIdx.x>>5, lane=threadIdx.x&31, wpb=blockDim.x>>5;
  float* st = stage + warp*2048;

  unsigned long long bias1 = pkab(b1S[2*lane], b1S[2*lane+1]);
  unsigned long long bias2 = pkab(b2S[2*lane], b2S[2*lane+1]);
  unsigned long long bias3 = pkab(b3S[lane],   b3S[32+lane]);
  float bias3s = b3S[64+lane];

  const int octs = EE/8;
  for (int p = blockIdx.x*wpb+warp; p<octs; p+=gridDim.x*wpb){
    long long e0 = 8LL*p;
    #pragma unroll
    for (int k=0;k<8;k++){
      const float* r = ele + (e0+k)*128;
      float* eE = st + k*256;
      #pragma unroll
      for (int c=0;c<4;c++) eE[c*32+lane]=r[c*32+lane];
    }
    __syncwarp();

    unsigned long long acc[8];
    #pragma unroll
    for (int k=0;k<8;k++) acc[k]=bias1;
    #pragma unroll 2
    for (int j=0;j<128;j+=4){
      unsigned long long w0=*(unsigned long long*)(sm+ (j  )*64 + 2*lane);
      unsigned long long w1=*(unsigned long long*)(sm+ (j+1)*64 + 2*lane);
      unsigned long long w2=*(unsigned long long*)(sm+ (j+2)*64 + 2*lane);
      unsigned long long w3=*(unsigned long long*)(sm+ (j+3)*64 + 2*lane);
      #pragma unroll
      for (int k=0;k<8;k++){
        float4 x = *(float4*)(st + k*256 + j);
        fma2(acc[k], pk2(x.x), w0);
        fma2(acc[k], pk2(x.y), w1);
        fma2(acc[k], pk2(x.z), w2);
        fma2(acc[k], pk2(x.w), w3);
      }
    }
    #pragma unroll
    for (int k=0;k<8;k++){
      float a0,a1; up2(acc[k],a0,a1);
      float* hE = st + k*256 + 128;
      hE[2*lane]=a0*sig_(a0); hE[2*lane+1]=a1*sig_(a1);
    }
    __syncwarp();

    #pragma unroll
    for (int k=0;k<8;k++) acc[k]=bias2;
    #pragma unroll 2
    for (int j=0;j<64;j+=4){
      unsigned long long w0=*(unsigned long long*)(sm+8192+(j  )*64 + 2*lane);
      unsigned long long w1=*(unsigned long long*)(sm+8192+(j+1)*64 + 2*lane);
      unsigned long long w2=*(unsigned long long*)(sm+8192+(j+2)*64 + 2*lane);
      unsigned long long w3=*(unsigned long long*)(sm+8192+(j+3)*64 + 2*lane);
      #pragma unroll
      for (int k=0;k<8;k++){
        float4 x = *(float4*)(st + k*256 + 128 + j);
        fma2(acc[k], pk2(x.x), w0);
        fma2(acc[k], pk2(x.y), w1);
        fma2(acc[k], pk2(x.z), w2);
        fma2(acc[k], pk2(x.w), w3);
      }
    }
    #pragma unroll
    for (int k=0;k<8;k++){
      float a0,a1; up2(acc[k],a0,a1);
      float* gE = st + k*256 + 192;
      gE[2*lane]=a0*sig_(a0); gE[2*lane+1]=a1*sig_(a1);
    }
    __syncwarp();

    unsigned long long c01[8]; float c2[8];
    #pragma unroll
    for (int k=0;k<8;k++){ c01[k]=bias3; c2[k]=bias3s; }
    #pragma unroll 2
    for (int j=0;j<64;j+=4){
      unsigned long long p0=*(unsigned long long*)(sm+12288+(j  )*64 + 2*lane);
      unsigned long long p1=*(unsigned long long*)(sm+12288+(j+1)*64 + 2*lane);
      unsigned long long p2=*(unsigned long long*)(sm+12288+(j+2)*64 + 2*lane);
      unsigned long long p3=*(unsigned long long*)(sm+12288+(j+3)*64 + 2*lane);
      float s0=sm[16384+(j  )*32+lane];
      float s1=sm[16384+(j+1)*32+lane];
      float s2=sm[16384+(j+2)*32+lane];
      float s3=sm[16384+(j+3)*32+lane];
      #pragma unroll
      for (int k=0;k<8;k++){
        float4 x = *(float4*)(st + k*256 + 192 + j);
        fma2(c01[k], pk2(x.x), p0); c2[k]+=x.x*s0;
        fma2(c01[k], pk2(x.y), p1); c2[k]+=x.y*s1;
        fma2(c01[k], pk2(x.z), p2); c2[k]+=x.z*s2;
        fma2(c01[k], pk2(x.w), p3); c2[k]+=x.w*s3;
      }
    }
    #pragma unroll
    for (int k=0;k<8;k++){
      float a,b; up2(c01[k],a,b);
      float* wo = g_wmlp + (e0+k)*96;
      wo[lane]=a; wo[32+lane]=b; wo[64+lane]=c2[k];
    }
    __syncwarp();
  }
}

// ---------------- E1: es-GEMV (64 -> 128) + P/Q gather, 16 edges/warp ----------------
__global__ void __launch_bounds__(512) k_e1(const int* __restrict__ eidx,
   const float* __restrict__ efea,
   const float* __restrict__ Wss0, const float* __restrict__ Wssg,
   const float* __restrict__ Wsv1){
  extern __shared__ float sm[];
  float4* FC = (float4*)sm;            // F1 rows 128..191: 64x32 f4 = 32KB
  float* stage = sm + 8192;            // per warp 2048 f (16 edges x 128 dup)

  for (int i=threadIdx.x;i<2048;i+=blockDim.x){
    int u=(i>>5)+128, l=i&31;
    FC[i]=make_float4(Wss0[u*64+2*l], Wss0[u*64+2*l+1], Wssg[u*32+l], Wsv1[u*32+l]);
  }
  __syncthreads();

  int warp=threadIdx.x>>5, lane=threadIdx.x&31, wpb=blockDim.x>>5;
  float* sd = stage + warp*2048;
  const int batches = EE/16;

  for (int p = blockIdx.x*wpb+warp; p<batches; p+=gridDim.x*wpb){
    int e0 = p*16;
    int nid[16], njd[16];
    #pragma unroll
    for (int k=0;k<16;k++){
      int e = e0+k;
      nid[k]=eidx[e]; njd[k]=eidx[EE+e];
      const float* r = efea + (long long)e*160;
      float x0=r[lane], x1=r[32+lane];
      *(unsigned long long*)(sd + k*128 + 2*lane)      = pkab(x0,x0);
      *(unsigned long long*)(sd + k*128 + 64 + 2*lane) = pkab(x1,x1);
    }
    __syncwarp();

    unsigned long long a01[16], agt[16];
    #pragma unroll
    for (int k=0;k<16;k++){ a01[k]=0ull; agt[k]=0ull; }
    #pragma unroll 2
    for (int u=0;u<64;u+=2){
      ulonglong2 w0 = *(ulonglong2*)&FC[(u  )*32+lane];
      ulonglong2 w1 = *(ulonglong2*)&FC[(u+1)*32+lane];
      #pragma unroll
      for (int k=0;k<16;k++){
        ulonglong2 xp = *(ulonglong2*)(sd + k*128 + 2*u);
        fma2(a01[k], xp.x, w0.x); fma2(agt[k], xp.x, w0.y);
        fma2(a01[k], xp.y, w1.x); fma2(agt[k], xp.y, w1.y);
      }
    }
    #pragma unroll
    for (int k=0;k<16;k++){
      float a0,a1,ag,at;
      up2(a01[k],a0,a1); up2(agt[k],ag,at);
      float4 P = *(const float4*)(g_P + nid[k]*128 + lane*4);
      float4 Q = *(const float4*)(g_Q + njd[k]*128 + lane*4);
      *(float4*)(g_e1 + (long long)(e0+k)*128 + lane*4) =
        make_float4(a0+P.x+Q.x, a1+P.y+Q.y, ag+P.z+Q.z, at+P.w+Q.w);
    }
    __syncwarp();
  }
}

// ---------------- E2: ev-GEMV (32 rows) + T/U epilogue + scatter, 8 edges/warp ----------------
__global__ void __launch_bounds__(512) k_e2(const int* __restrict__ eidx,
   const float* __restrict__ esh, const float* __restrict__ efea,
   const float* __restrict__ Wvv0, const float* __restrict__ Wvvg,
   const float* __restrict__ Wvs1){
  extern __shared__ float sm[];
  // W2a: ulonglong2[32*32] = (w0,w1),(wz,ww) for F2 rows 64..95 : 4096 f
  // W2b: ull[32*32] = (ww,ww) dup : 2048 f
  ulonglong2* W2a = (ulonglong2*)sm;
  unsigned long long* W2b = (unsigned long long*)(sm+4096);
  float* stage = sm + 6144;            // per warp 2080 f (8 edges x 256 + sh 32)

  for (int i=threadIdx.x;i<1024;i+=blockDim.x){
    int u=(i>>5)+64, l=i&31;
    float w0=Wvv0[u*64+2*l], w1=Wvv0[u*64+2*l+1];
    float wz=Wvvg[u*32+l],   ww=Wvs1[u*32+l];
    W2a[i] = make_ulonglong2(pkab(w0,w1), pkab(wz,ww));
    W2b[i] = pkab(ww,ww);
  }
  __syncthreads();

  int warp=threadIdx.x>>5, lane=threadIdx.x&31, wpb=blockDim.x>>5;
  float* sd  = stage + warp*2080;      // 8 x 256
  float* shS = sd + 2048;              // 8 x 4
  const float inv3 = 0.57735027f, invfan = 0.058925565f;
  const int batches = EE/8;

  for (int p = blockIdx.x*wpb+warp; p<batches; p+=gridDim.x*wpb){
    int e0 = p*8;
    int nid[8], njd[8];
    #pragma unroll
    for (int k=0;k<8;k++){
      int e = e0+k;
      nid[k]=eidx[e]; njd[k]=eidx[EE+e];
      float4 sh = *(const float4*)(esh + (long long)e*4);
      if (lane==0) *(float4*)(shS + k*4) = sh;
      const float* r = efea + (long long)e*160;
      float ex=r[64+3*lane], ey=r[65+3*lane], ez=r[66+3*lane];
      float dd=(ex*sh.y+ey*sh.z+ez*sh.w)*inv3;
      float* o = sd + k*256 + lane*8;
      *(float4*)o     = make_float4(dd,dd,ex,ey);
      *(float2*)(o+4) = make_float2(dd,ez);
    }
    __syncwarp();

    unsigned long long b01[8], r01[8], gz2[8];
    #pragma unroll
    for (int k=0;k<8;k++){ b01[k]=0ull; r01[k]=0ull; gz2[k]=0ull; }
    #pragma unroll 4
    for (int u=0;u<32;u++){
      ulonglong2 wa = W2a[u*32+lane];
      unsigned long long wb = W2b[u*32+lane];
      #pragma unroll
      for (int k=0;k<8;k++){
        ulonglong2 t1 = *(ulonglong2*)(sd + k*256 + u*8);
        unsigned long long t2 = *(unsigned long long*)(sd + k*256 + u*8 + 4);
        fma2(b01[k], t1.x, wa.x);   // (dd,dd)*(w0,w1)
        fma2(r01[k], t1.y, wb);     // (ex,ey)*(ww,ww)
        fma2(gz2[k], t2,   wa.y);   // (dd,ez)*(wz,ww) -> (bg, r2)
      }
    }

    #pragma unroll
    for (int k=0;k<8;k++){
      long long e = e0+k;
      float b0,b1,r0,r1,bg,r2;
      up2(b01[k],b0,b1); up2(r01[k],r0,r1); up2(gz2[k],bg,r2);
      float4 sh = *(float4*)(shS + k*4);
      const float* tp = g_T + nid[k]*384 + lane*12;
      const float* upt = g_U + njd[k]*384 + lane*12;
      float4 t0=*(const float4*)tp,  t1=*(const float4*)(tp+4),  t2=*(const float4*)(tp+8);
      float4 u0=*(const float4*)upt, u1=*(const float4*)(upt+4), u2=*(const float4*)(upt+8);
      float s0x=t0.x+u0.x, s0y=t0.y+u0.y, s0z=t0.z+u0.z, s0w=t0.w+u0.w;
      float s1x=t1.x+u1.x, s1y=t1.y+u1.y, s1z=t1.z+u1.z, s1w=t1.w+u1.w;
      float s2x=t2.x+u2.x, s2y=t2.y+u2.y, s2z=t2.z+u2.z, s2w=t2.w+u2.w;
      b0 += inv3*(s0x*sh.y + s0y*sh.z + s0z*sh.w);
      b1 += inv3*(s0w*sh.y + s1x*sh.z + s1y*sh.w);
      bg += inv3*(s1z*sh.y + s1w*sh.z + s2x*sh.w);
      r0 += s2y; r1 += s2z; r2 += s2w;

      float4 f1v = *(const float4*)(g_e1 + e*128 + lane*4);  // a0,a1,ag,at
      float zs0=(sh.x*f1v.x+b0)*invfan, zs1=(sh.x*f1v.y+b1)*invfan;
      float zg =(sh.x*f1v.z+bg)*invfan;
      float at = f1v.w;
      const float* wm = g_wmlp + e*96;
      float2 wm01 = *(const float2*)(wm+2*lane);
      float wmv = wm[64+lane];
      zs0 = zs0*sig_(zs0)*wm01.x;
      zs1 = zs1*sig_(zs1)*wm01.y;
      float gv = sig_(zg)*wmv*invfan;
      int n = nid[k];
      atomicAdd(&g_accs[n*64+2*lane],   zs0);
      atomicAdd(&g_accs[n*64+2*lane+1], zs1);
      atomicAdd(&g_accv[n*96+3*lane],   (at*sh.y + r0*sh.x)*gv);
      atomicAdd(&g_accv[n*96+3*lane+1], (at*sh.z + r1*sh.x)*gv);
      atomicAdd(&g_accv[n*96+3*lane+2], (at*sh.w + r2*sh.x)*gv);
    }
    __syncwarp();
  }
}

// ---------------- node post ----------------
__global__ void __launch_bounds__(512) k_node_post(const int* __restrict__ batch,
   const float* __restrict__ ppWs, const float* __restrict__ ppbs,
   const float* __restrict__ ppWv){
  extern __shared__ float sm[];
  float2* WsS = (float2*)sm;
  float* WvS = sm+4096;
  float* bsS = sm+5120;
  float* stage = sm+5184;
  for (int i=threadIdx.x;i<4096;i+=blockDim.x) sm[i]=ppWs[i];
  for (int i=threadIdx.x;i<1024;i+=blockDim.x) WvS[i]=ppWv[i];
  for (int i=threadIdx.x;i<64;i+=blockDim.x) bsS[i]=ppbs[i];
  __syncthreads();
  int warp=threadIdx.x>>5, lane=threadIdx.x&31, wpb=blockDim.x>>5;
  float*  sS  = stage + warp*192;
  float4* vS  = (float4*)(sS+64);
  for (int n=blockIdx.x*wpb+warp; n<NN; n+=gridDim.x*wpb){
    sS[lane]=g_accs[n*64+lane]; sS[32+lane]=g_accs[n*64+32+lane];
    vS[lane]=make_float4(g_accv[n*96+3*lane],g_accv[n*96+3*lane+1],g_accv[n*96+3*lane+2],0.f);
    __syncwarp();
    float a0=0.f,a1=0.f;
    #pragma unroll 4
    for (int u=0;u<64;u++){
      float x=sS[u]; float2 w=WsS[u*32+lane];
      a0+=x*w.x; a1+=x*w.y;
    }
    float ns0 = a0*0.125f + bsS[2*lane]   + g_scs[n*64+2*lane];
    float ns1 = a1*0.125f + bsS[2*lane+1] + g_scs[n*64+2*lane+1];
    g_ns[n*64+2*lane]=ns0; g_ns[n*64+2*lane+1]=ns1;
    float vx=0.f,vy=0.f,vz=0.f;
    #pragma unroll 4
    for (int u=0;u<32;u++){
      float4 x=vS[u]; float w=WvS[u*32+lane];
      vx+=x.x*w; vy+=x.y*w; vz+=x.z*w;
    }
    float nv0 = vx*0.17677670f + g_scv[n*96+3*lane];
    float nv1 = vy*0.17677670f + g_scv[n*96+3*lane+1];
    float nv2 = vz*0.17677670f + g_scv[n*96+3*lane+2];
    g_nv[n*96+3*lane]=nv0; g_nv[n*96+3*lane+1]=nv1; g_nv[n*96+3*lane+2]=nv2;
    float m = ns0+ns1;
    float q = ns0*ns0+ns1*ns1;
    float pw = nv0*nv0+nv1*nv1+nv2*nv2;
    #pragma unroll
    for (int off=16;off>0;off>>=1){
      m += __shfl_down_sync(0xffffffffu, m, off);
      q += __shfl_down_sync(0xffffffffu, q, off);
      pw += __shfl_down_sync(0xffffffffu, pw, off);
    }
    if (lane==0){
      int g = batch[n];
      atomicAdd(&g_gstat[g],        m*(1.f/64.f));
      atomicAdd(&g_gstat[NG_+g],    q*(1.f/64.f));
      atomicAdd(&g_gstat[2*NG_+g],  pw*(1.f/96.f));
      atomicAdd(&g_gstat[3*NG_+g],  1.f);
    }
    __syncwarp();
  }
}

// ---------------- group finalize ----------------
__global__ void k_groups(){
  int t = threadIdx.x;
  if (t < NG_){
    float c  = fmaxf(g_gstat[3*NG_+t], 1.f);
    float mu = g_gstat[t]/c;
    float vs = g_gstat[NG_+t]/c - mu*mu;
    float vv = g_gstat[2*NG_+t]/c;
    g_gout[t]       = mu;
    g_gout[NG_+t]   = rsqrtf(vs+1e-5f);
    g_gout[2*NG_+t] = rsqrtf(vv+1e-5f);
  }
}

// ---------------- apply norm + residual ----------------
__global__ void k_out(const float* __restrict__ nf, const int* __restrict__ batch,
   const float* __restrict__ lnws, const float* __restrict__ lnbs,
   const float* __restrict__ lnwv, float* __restrict__ out){
  int i = blockIdx.x*blockDim.x+threadIdx.x;
  if (i >= NN*160) return;
  int n = i/160, c = i - n*160;
  int g = batch[n];
  float base = nf[i];
  float o;
  if (c < 64){
    float x = (g_ns[n*64+c] - g_gout[g]) * g_gout[NG_+g];
    o = base + x*lnws[c] + lnbs[c];
  } else {
    int cc = c-64;
    o = base + g_nv[n*96+cc]*g_gout[2*NG_+g]*lnwv[cc/3];
  }
  out[i]=o;
}

// ---------------- launcher ----------------
extern "C" void kernel_launch(void* const* d_in, const int* in_sizes, int n_in,
                              void* d_out, int out_size){
  const float* nf   =(const float*)d_in[0];
  const float* oh   =(const float*)d_in[1];
  const float* esh  =(const float*)d_in[2];
  const float* efea =(const float*)d_in[3];
  const float* ele  =(const float*)d_in[4];
  const int*   eidx =(const int*)d_in[5];
  const int*   batch=(const int*)d_in[6];
  const float* lpWs =(const float*)d_in[7];
  const float* lpbs =(const float*)d_in[8];
  const float* lpWv =(const float*)d_in[9];
  const float* ppWs =(const float*)d_in[10];
  const float* ppbs =(const float*)d_in[11];
  const float* ppWv =(const float*)d_in[12];
  const float* scWs =(const float*)d_in[13];
  const float* scWv =(const float*)d_in[14];
  const float* Wss0 =(const float*)d_in[15];
  const float* Wvv0 =(const float*)d_in[16];
  const float* Wssg =(const float*)d_in[17];
  const float* Wvvg =(const float*)d_in[18];
  const float* Wsv1 =(const float*)d_in[19];
  const float* Wvs1 =(const float*)d_in[20];
  const float* fcW1 =(const float*)d_in[21];
  const float* fcb1 =(const float*)d_in[22];
  const float* fcW2 =(const float*)d_in[23];
  const float* fcb2 =(const float*)d_in[24];
  const float* fcW3 =(const float*)d_in[25];
  const float* fcb3 =(const float*)d_in[26];
  const float* lnws =(const float*)d_in[27];
  const float* lnbs =(const float*)d_in[28];
  const float* lnwv =(const float*)d_in[29];
  float* out = (float*)d_out;

  const int SM_PRE  = (25664 + 16*192)*4;    // 114944
  const int SM_PS   = (16384 + 16*1024)*4;   // 131072
  const int SM_TV   = (8192  + 16*512)*4;    // 65536
  const int SM_MLP  = (18656 + 16*2048)*4;   // 205696
  const int SM_E1   = (8192  + 16*2048)*4;   // 163840
  const int SM_E2   = (6144  + 16*2080)*4;   // 157696
  const int SM_POST = (5184  + 16*192)*4;    // 33024
  cudaFuncSetAttribute(k_node_pre,  cudaFuncAttributeMaxDynamicSharedMemorySize, SM_PRE);
  cudaFuncSetAttribute(k_ps,        cudaFuncAttributeMaxDynamicSharedMemorySize, SM_PS);
  cudaFuncSetAttribute(k_tv,        cudaFuncAttributeMaxDynamicSharedMemorySize, SM_TV);
  cudaFuncSetAttribute(k_mlp,       cudaFuncAttributeMaxDynamicSharedMemorySize, SM_MLP);
  cudaFuncSetAttribute(k_e1,        cudaFuncAttributeMaxDynamicSharedMemorySize, SM_E1);
  cudaFuncSetAttribute(k_e2,        cudaFuncAttributeMaxDynamicSharedMemorySize, SM_E2);
  cudaFuncSetAttribute(k_node_post, cudaFuncAttributeMaxDynamicSharedMemorySize, SM_POST);

  k_zero<<<(NN*160 + 4*NG_ + 255)/256, 256>>>();
  k_node_pre<<<148, 512, SM_PRE>>>(nf, oh, lpWs, lpbs, lpWv, scWs, scWv);
  k_ps<<<148, 512, SM_PS>>>(Wss0, Wssg, Wsv1);
  k_tv<<<148, 512, SM_TV>>>(Wvv0, Wvvg, Wvs1);
  k_mlp<<<296, 512, SM_MLP>>>(ele, fcW1, fcb1, fcW2, fcb2, fcW3, fcb3);
  k_e1<<<296, 512, SM_E1>>>(eidx, efea, Wss0, Wssg, Wsv1);
  k_e2<<<296, 512, SM_E2>>>(eidx, esh, efea, Wvv0, Wvvg, Wvs1);
  k_node_post<<<148, 512, SM_POST>>>(batch, ppWs, ppbs, ppWv);
  k_groups<<<1, 32>>>();
  k_out<<<(NN*160 + 255)/256, 256>>>(nf, batch, lnws, lnbs, lnwv, out);
}